// round 1
// baseline (speedup 1.0000x reference)
#include <cuda_runtime.h>

#define NN 100000
#define NE 3200000
#define NL 200000

// ---------------- scratch (device globals, no runtime allocation) ----------
__device__ __align__(16) float g_inv[NN];          // 1/sqrt(deg)
__device__ int                 g_deg[NN];
__device__ float               g_norm[NE];         // per-edge norm
__device__ __align__(16) float g_agg1[NN * 4];     // aggregated x  [N,4]
__device__ __align__(16) float g_hW2[NN * 64];     // (relu(aggx@W1+b1))@W2
__device__ __align__(16) float g_agg2[NN * 64];    // aggregated hW2
__device__ __align__(16) float g_z[NN * 64];       // final node embeddings

__device__ __forceinline__ void red_add_v4(float* a, float x, float y, float z, float w) {
    asm volatile("red.global.add.v4.f32 [%0], {%1, %2, %3, %4};"
                 :: "l"(a), "f"(x), "f"(y), "f"(z), "f"(w) : "memory");
}

// ---------------- 1) zero scratch -------------------------------------------
__global__ void k_zero() {
    int i = blockIdx.x * blockDim.x + threadIdx.x;      // grid covers NN*16
    if (i < NN * 16) reinterpret_cast<float4*>(g_agg2)[i] = make_float4(0.f, 0.f, 0.f, 0.f);
    if (i < NN) {
        reinterpret_cast<float4*>(g_agg1)[i] = make_float4(0.f, 0.f, 0.f, 0.f);
        g_deg[i] = 0;
    }
}

// ---------------- 2) degree -------------------------------------------------
__global__ void k_deg(const int* __restrict__ ei) {
    int i = blockIdx.x * blockDim.x + threadIdx.x;
    if (i < NE) atomicAdd(&g_deg[ei[NE + i]], 1);       // dst row
}

// ---------------- 3) inv sqrt degree ----------------------------------------
__global__ void k_inv() {
    int i = blockIdx.x * blockDim.x + threadIdx.x;
    if (i < NN) g_inv[i] = rsqrtf((float)g_deg[i] + 1.0f);  // +1 self loop
}

// ---------------- 4) layer-1 scatter (4-wide) + edge norm -------------------
__global__ void k_scatter1(const int* __restrict__ ei, const float* __restrict__ x) {
    int i = blockIdx.x * blockDim.x + threadIdx.x;
    if (i >= NE) return;
    int s = ei[i];
    int d = ei[NE + i];
    float nm = g_inv[s] * g_inv[d];
    g_norm[i] = nm;
    float4 xv = reinterpret_cast<const float4*>(x)[s];
    red_add_v4(&g_agg1[d * 4], xv.x * nm, xv.y * nm, xv.z * nm, xv.w * nm);
}

// ---------------- 5) fused dense: h = relu(a@W1+b1); hW2 = h@W2 -------------
// 128 threads = 4 warps, each warp handles 4 nodes -> 16 nodes/block, 6250 blocks.
__global__ __launch_bounds__(128) void k_layer12(const float* __restrict__ x,
                                                 const float* __restrict__ W1,
                                                 const float* __restrict__ b1,
                                                 const float* __restrict__ W2) {
    __shared__ float sW2[128 * 64];        // 32 KB
    __shared__ float sh[4][4][128];        // 8 KB: [warp][node][k]

    int tid  = threadIdx.x;
    int lane = tid & 31;
    int w    = tid >> 5;
    int k0   = lane * 4;

    #pragma unroll
    for (int i = tid; i < 128 * 64; i += 128) sW2[i] = W2[i];

    float rW1[4][4], rb1[4];
    #pragma unroll
    for (int c = 0; c < 4; c++)
        #pragma unroll
        for (int u = 0; u < 4; u++) rW1[c][u] = W1[c * 128 + k0 + u];
    #pragma unroll
    for (int u = 0; u < 4; u++) rb1[u] = b1[k0 + u];
    __syncthreads();

    int nb = (blockIdx.x * 4 + w) * 4;     // first node of this warp (exact tiling)

    #pragma unroll
    for (int n = 0; n < 4; n++) {
        int node  = nb + n;
        float inv = g_inv[node];
        float i2  = inv * inv;
        float4 a  = reinterpret_cast<const float4*>(g_agg1)[node];
        float4 xv = reinterpret_cast<const float4*>(x)[node];
        a.x = fmaf(xv.x, i2, a.x);
        a.y = fmaf(xv.y, i2, a.y);
        a.z = fmaf(xv.z, i2, a.z);
        a.w = fmaf(xv.w, i2, a.w);
        #pragma unroll
        for (int u = 0; u < 4; u++) {
            float h = rb1[u];
            h = fmaf(a.x, rW1[0][u], h);
            h = fmaf(a.y, rW1[1][u], h);
            h = fmaf(a.z, rW1[2][u], h);
            h = fmaf(a.w, rW1[3][u], h);
            sh[w][n][k0 + u] = fmaxf(h, 0.0f);
        }
    }
    __syncwarp();

    float acc[4][2];
    #pragma unroll
    for (int n = 0; n < 4; n++) { acc[n][0] = 0.f; acc[n][1] = 0.f; }

    #pragma unroll 16
    for (int k = 0; k < 128; k++) {
        float w0 = sW2[k * 64 + lane];          // conflict-free: bank = lane
        float w1 = sW2[k * 64 + lane + 32];
        #pragma unroll
        for (int n = 0; n < 4; n++) {
            float hk = sh[w][n][k];             // broadcast
            acc[n][0] = fmaf(hk, w0, acc[n][0]);
            acc[n][1] = fmaf(hk, w1, acc[n][1]);
        }
    }

    #pragma unroll
    for (int n = 0; n < 4; n++) {
        int node = nb + n;
        g_hW2[node * 64 + lane]      = acc[n][0];
        g_hW2[node * 64 + lane + 32] = acc[n][1];
    }
}

// ---------------- 6) layer-2 scatter (64-wide), 16 threads/edge -------------
__global__ __launch_bounds__(256) void k_scatter2(const int* __restrict__ ei) {
    unsigned t = blockIdx.x * 256u + threadIdx.x;       // NE*16 threads
    int e = t >> 4;
    int c = t & 15;
    int s = ei[e];
    int d = ei[NE + e];
    float nm = g_norm[e];
    float4 v = reinterpret_cast<const float4*>(g_hW2)[s * 16 + c];
    red_add_v4(&g_agg2[d * 64 + c * 4], v.x * nm, v.y * nm, v.z * nm, v.w * nm);
}

// ---------------- 7) finalize z = agg2 + self*hW2 + b2 ----------------------
__global__ void k_zfinal(const float* __restrict__ b2) {
    int i = blockIdx.x * blockDim.x + threadIdx.x;      // NN*16 float4s
    if (i >= NN * 16) return;
    int node = i >> 4;
    int c    = i & 15;
    float inv = g_inv[node];
    float i2  = inv * inv;
    float4 a  = reinterpret_cast<const float4*>(g_agg2)[i];
    float4 h  = reinterpret_cast<const float4*>(g_hW2)[i];
    float4 bb = reinterpret_cast<const float4*>(b2)[c];
    float4 o;
    o.x = fmaf(h.x, i2, a.x) + bb.x;
    o.y = fmaf(h.y, i2, a.y) + bb.y;
    o.z = fmaf(h.z, i2, a.z) + bb.z;
    o.w = fmaf(h.w, i2, a.w) + bb.w;
    reinterpret_cast<float4*>(g_z)[i] = o;
}

// ---------------- 8) decode: logits[e] = dot(z[a], z[b]) --------------------
__global__ __launch_bounds__(256) void k_decode(const int* __restrict__ eli,
                                                float* __restrict__ out) {
    unsigned t = blockIdx.x * 256u + threadIdx.x;       // NL*16 threads
    int e = t >> 4;
    int c = t & 15;
    int a = eli[e];
    int b = eli[NL + e];
    float4 za = reinterpret_cast<const float4*>(g_z)[a * 16 + c];
    float4 zb = reinterpret_cast<const float4*>(g_z)[b * 16 + c];
    float p = za.x * zb.x + za.y * zb.y + za.z * zb.z + za.w * zb.w;
    #pragma unroll
    for (int o = 8; o >= 1; o >>= 1) p += __shfl_xor_sync(0xffffffffu, p, o);
    if (c == 0) out[e] = p;
}

// ---------------- launch -----------------------------------------------------
extern "C" void kernel_launch(void* const* d_in, const int* in_sizes, int n_in,
                              void* d_out, int out_size) {
    const float* x   = (const float*)d_in[0];
    const int*   ei  = (const int*)  d_in[1];
    const int*   eli = (const int*)  d_in[2];
    const float* W1  = (const float*)d_in[3];
    const float* b1  = (const float*)d_in[4];
    const float* W2  = (const float*)d_in[5];
    const float* b2  = (const float*)d_in[6];
    float* out = (float*)d_out;

    k_zero    <<<(NN * 16 + 255) / 256, 256>>>();
    k_deg     <<<(NE + 255) / 256, 256>>>(ei);
    k_inv     <<<(NN + 255) / 256, 256>>>();
    k_scatter1<<<(NE + 255) / 256, 256>>>(ei, x);
    k_layer12 <<<NN / 16, 128>>>(x, W1, b1, W2);
    k_scatter2<<<(NE * 16) / 256, 256>>>(ei);
    k_zfinal  <<<(NN * 16 + 255) / 256, 256>>>(b2);
    k_decode  <<<(NL * 16) / 256, 256>>>(eli, out);
}

// round 2
// speedup vs baseline: 1.3548x; 1.3548x over previous
#include <cuda_runtime.h>

#define NN 100000
#define NE 3200000
#define NL 200000
#define SCAN_B 1024
#define NBLK ((NN + SCAN_B - 1) / SCAN_B)   // 98

// ---------------- scratch (device globals) ----------------------------------
__device__ int                 g_deg[NN];
__device__ float               g_inv[NN];
__device__ int                 g_loc[NN];        // block-local exclusive scan
__device__ int                 g_bsum[NBLK];
__device__ int                 g_bsumex[NBLK];
__device__ int                 g_rowptr[NN];
__device__ int                 g_fill[NN];
__device__ __align__(8)  int2  g_csr[NE];        // (src, norm bits), dst-grouped
__device__ __align__(16) float g_agg1[NN * 4];
__device__ __align__(16) float g_hW2[NN * 64];
__device__ __align__(16) float g_z[NN * 64];

// ---------------- 1) zero degree --------------------------------------------
__global__ void k_zero() {
    int i = blockIdx.x * blockDim.x + threadIdx.x;
    if (i < NN) g_deg[i] = 0;
}

// ---------------- 2) degree count -------------------------------------------
__global__ void k_deg(const int* __restrict__ ei) {
    int i = blockIdx.x * blockDim.x + threadIdx.x;   // NE/256 exact
    atomicAdd(&g_deg[ei[NE + i]], 1);
}

// ---------------- 3) scan phase 1: per-block inclusive scan -----------------
__global__ __launch_bounds__(SCAN_B) void k_scan1() {
    int i = blockIdx.x * SCAN_B + threadIdx.x;
    int v = (i < NN) ? g_deg[i] : 0;
    int lane = threadIdx.x & 31, w = threadIdx.x >> 5;
    int s = v;
    #pragma unroll
    for (int o = 1; o < 32; o <<= 1) {
        int t = __shfl_up_sync(0xffffffffu, s, o);
        if (lane >= o) s += t;
    }
    __shared__ int wsum[32];
    if (lane == 31) wsum[w] = s;
    __syncthreads();
    if (w == 0) {
        int ws = wsum[lane];
        #pragma unroll
        for (int o = 1; o < 32; o <<= 1) {
            int t = __shfl_up_sync(0xffffffffu, ws, o);
            if (lane >= o) ws += t;
        }
        wsum[lane] = ws;
    }
    __syncthreads();
    int excl = s - v + (w > 0 ? wsum[w - 1] : 0);
    if (i < NN) g_loc[i] = excl;
    if (threadIdx.x == 0) g_bsum[blockIdx.x] = wsum[31];
}

// ---------------- 4) scan phase 2: scan block sums (single block) -----------
__global__ void k_scan2() {
    int i = threadIdx.x;                 // 128 threads
    int v = (i < NBLK) ? g_bsum[i] : 0;
    int lane = i & 31, w = i >> 5;
    int s = v;
    #pragma unroll
    for (int o = 1; o < 32; o <<= 1) {
        int t = __shfl_up_sync(0xffffffffu, s, o);
        if (lane >= o) s += t;
    }
    __shared__ int ws[4];
    if (lane == 31) ws[w] = s;
    __syncthreads();
    int add = 0;
    for (int k = 0; k < w; k++) add += ws[k];
    if (i < NBLK) g_bsumex[i] = s - v + add;
}

// ---------------- 5) scan phase 3: rowptr, fill counters, inv ---------------
__global__ void k_scan3() {
    int i = blockIdx.x * blockDim.x + threadIdx.x;
    if (i >= NN) return;
    int rp = g_loc[i] + g_bsumex[i >> 10];
    g_rowptr[i] = rp;
    g_fill[i]   = rp;
    g_inv[i]    = rsqrtf((float)g_deg[i] + 1.0f);   // +1 self loop
}

// ---------------- 6) CSR fill -----------------------------------------------
__global__ void k_fill(const int* __restrict__ ei) {
    int e = blockIdx.x * blockDim.x + threadIdx.x;   // NE/256 exact
    int s = ei[e];
    int d = ei[NE + e];
    int pos = atomicAdd(&g_fill[d], 1);
    float nm = g_inv[s] * g_inv[d];
    g_csr[pos] = make_int2(s, __float_as_int(nm));
}

// ---------------- 7) layer-1 gather: warp per node ---------------------------
__global__ __launch_bounds__(256) void k_gather1(const float* __restrict__ x) {
    int node = (blockIdx.x * 256 + threadIdx.x) >> 5;  // 12500 blocks exact
    int lane = threadIdx.x & 31;
    int start = g_rowptr[node];
    int deg   = g_deg[node];
    float4 acc = make_float4(0.f, 0.f, 0.f, 0.f);
    for (int j = lane; j < deg; j += 32) {
        int2 en = g_csr[start + j];
        float nm = __int_as_float(en.y);
        float4 xv = reinterpret_cast<const float4*>(x)[en.x];
        acc.x = fmaf(xv.x, nm, acc.x);
        acc.y = fmaf(xv.y, nm, acc.y);
        acc.z = fmaf(xv.z, nm, acc.z);
        acc.w = fmaf(xv.w, nm, acc.w);
    }
    #pragma unroll
    for (int o = 16; o >= 1; o >>= 1) {
        acc.x += __shfl_xor_sync(0xffffffffu, acc.x, o);
        acc.y += __shfl_xor_sync(0xffffffffu, acc.y, o);
        acc.z += __shfl_xor_sync(0xffffffffu, acc.z, o);
        acc.w += __shfl_xor_sync(0xffffffffu, acc.w, o);
    }
    if (lane == 0) reinterpret_cast<float4*>(g_agg1)[node] = acc;
}

// ---------------- 8) fused dense: hW2 = (relu(agg@W1+b1))@W2 -----------------
// 128 threads = 4 warps; each warp 4 nodes per iteration, 4 iterations = 64 nodes/block.
__global__ __launch_bounds__(128) void k_layer12(const float* __restrict__ x,
                                                 const float* __restrict__ W1,
                                                 const float* __restrict__ b1,
                                                 const float* __restrict__ W2) {
    __shared__ float sW2[128 * 64];        // 32 KB
    __shared__ float sh[4][4][128];        // 8 KB

    int tid  = threadIdx.x;
    int lane = tid & 31;
    int w    = tid >> 5;
    int k0   = lane * 4;

    for (int i = tid; i < 128 * 64; i += 128) sW2[i] = W2[i];

    float rW1[4][4], rb1[4];
    #pragma unroll
    for (int c = 0; c < 4; c++)
        #pragma unroll
        for (int u = 0; u < 4; u++) rW1[c][u] = W1[c * 128 + k0 + u];
    #pragma unroll
    for (int u = 0; u < 4; u++) rb1[u] = b1[k0 + u];
    __syncthreads();

    for (int it = 0; it < 4; it++) {
        int nb = blockIdx.x * 64 + it * 16 + w * 4;

        #pragma unroll
        for (int n = 0; n < 4; n++) {
            int node = nb + n;
            if (node < NN) {
                float inv = g_inv[node];
                float i2  = inv * inv;
                float4 a  = reinterpret_cast<const float4*>(g_agg1)[node];
                float4 xv = reinterpret_cast<const float4*>(x)[node];
                a.x = fmaf(xv.x, i2, a.x);
                a.y = fmaf(xv.y, i2, a.y);
                a.z = fmaf(xv.z, i2, a.z);
                a.w = fmaf(xv.w, i2, a.w);
                float4 hv;
                float* hp = &hv.x;
                #pragma unroll
                for (int u = 0; u < 4; u++) {
                    float h = rb1[u];
                    h = fmaf(a.x, rW1[0][u], h);
                    h = fmaf(a.y, rW1[1][u], h);
                    h = fmaf(a.z, rW1[2][u], h);
                    h = fmaf(a.w, rW1[3][u], h);
                    hp[u] = fmaxf(h, 0.0f);
                }
                *reinterpret_cast<float4*>(&sh[w][n][k0]) = hv;   // STS.128, conflict-free
            }
        }
        __syncwarp();

        float acc[4][2];
        #pragma unroll
        for (int n = 0; n < 4; n++) { acc[n][0] = 0.f; acc[n][1] = 0.f; }

        #pragma unroll 16
        for (int k = 0; k < 128; k++) {
            float w0 = sW2[k * 64 + lane];
            float w1 = sW2[k * 64 + lane + 32];
            #pragma unroll
            for (int n = 0; n < 4; n++) {
                float hk = sh[w][n][k];
                acc[n][0] = fmaf(hk, w0, acc[n][0]);
                acc[n][1] = fmaf(hk, w1, acc[n][1]);
            }
        }

        #pragma unroll
        for (int n = 0; n < 4; n++) {
            int node = nb + n;
            if (node < NN) {
                g_hW2[node * 64 + lane]      = acc[n][0];
                g_hW2[node * 64 + lane + 32] = acc[n][1];
            }
        }
        __syncwarp();
    }
}

// ---------------- 9) layer-2 gather (64-wide) fused with finalize ------------
__global__ __launch_bounds__(256) void k_gather2z(const float* __restrict__ b2) {
    unsigned t = blockIdx.x * 256u + threadIdx.x;   // NN*16 threads, 6250 blocks
    int node = t >> 4;
    int c    = t & 15;
    int start = g_rowptr[node];
    int deg   = g_deg[node];
    float inv = g_inv[node];
    float i2  = inv * inv;

    // self term
    float4 self = reinterpret_cast<const float4*>(g_hW2)[node * 16 + c];
    float4 acc;
    acc.x = self.x * i2; acc.y = self.y * i2;
    acc.z = self.z * i2; acc.w = self.w * i2;

    for (int j = 0; j < deg; j++) {
        int2 en = g_csr[start + j];                 // broadcast across 16 lanes
        float nm = __int_as_float(en.y);
        float4 v = reinterpret_cast<const float4*>(g_hW2)[en.x * 16 + c];
        acc.x = fmaf(v.x, nm, acc.x);
        acc.y = fmaf(v.y, nm, acc.y);
        acc.z = fmaf(v.z, nm, acc.z);
        acc.w = fmaf(v.w, nm, acc.w);
    }

    float4 bb = reinterpret_cast<const float4*>(b2)[c];
    acc.x += bb.x; acc.y += bb.y; acc.z += bb.z; acc.w += bb.w;
    reinterpret_cast<float4*>(g_z)[t] = acc;
}

// ---------------- 10) decode --------------------------------------------------
__global__ __launch_bounds__(256) void k_decode(const int* __restrict__ eli,
                                                float* __restrict__ out) {
    unsigned t = blockIdx.x * 256u + threadIdx.x;   // NL*16 threads
    int e = t >> 4;
    int c = t & 15;
    int a = eli[e];
    int b = eli[NL + e];
    float4 za = reinterpret_cast<const float4*>(g_z)[a * 16 + c];
    float4 zb = reinterpret_cast<const float4*>(g_z)[b * 16 + c];
    float p = za.x * zb.x + za.y * zb.y + za.z * zb.z + za.w * zb.w;
    #pragma unroll
    for (int o = 8; o >= 1; o >>= 1) p += __shfl_xor_sync(0xffffffffu, p, o);
    if (c == 0) out[e] = p;
}

// ---------------- launch -------------------------------------------------------
extern "C" void kernel_launch(void* const* d_in, const int* in_sizes, int n_in,
                              void* d_out, int out_size) {
    const float* x   = (const float*)d_in[0];
    const int*   ei  = (const int*)  d_in[1];
    const int*   eli = (const int*)  d_in[2];
    const float* W1  = (const float*)d_in[3];
    const float* b1  = (const float*)d_in[4];
    const float* W2  = (const float*)d_in[5];
    const float* b2  = (const float*)d_in[6];
    float* out = (float*)d_out;

    k_zero    <<<(NN + 255) / 256, 256>>>();
    k_deg     <<<NE / 256, 256>>>(ei);
    k_scan1   <<<NBLK, SCAN_B>>>();
    k_scan2   <<<1, 128>>>();
    k_scan3   <<<(NN + 255) / 256, 256>>>();
    k_fill    <<<NE / 256, 256>>>(ei);
    k_gather1 <<<NN * 32 / 256, 256>>>(x);
    k_layer12 <<<(NN + 63) / 64, 128>>>(x, W1, b1, W2);
    k_gather2z<<<NN * 16 / 256, 256>>>(b2);
    k_decode  <<<NL * 16 / 256, 256>>>(eli, out);
}

// round 3
// speedup vs baseline: 1.4782x; 1.0910x over previous
#include <cuda_runtime.h>
#include <cuda_fp16.h>

#define NN 100000
#define NE 3200000
#define NL 200000
#define SCAN_B 1024
#define NBLK ((NN + SCAN_B - 1) / SCAN_B)   // 98

// ---------------- scratch (device globals) ----------------------------------
__device__ int                 g_deg[NN];
__device__ float               g_inv[NN];
__device__ int                 g_loc[NN];
__device__ int                 g_bsum[NBLK];
__device__ int                 g_bsumex[NBLK];
__device__ int                 g_rowptr[NN];
__device__ int                 g_fill[NN];
__device__ __align__(8)  int2  g_csr[NE];        // (src, norm bits), dst-grouped
__device__ __align__(16) float g_agg1[NN * 4];
__device__ __align__(16) float g_hW2[NN * 64];   // fp32 (self term)
__device__ __align__(16) __half g_hW2h[NN * 64]; // fp16 (neighbor gather)
__device__ __align__(16) float g_z[NN * 64];

// ---------------- 1) zero degree --------------------------------------------
__global__ void k_zero() {
    int i = blockIdx.x * blockDim.x + threadIdx.x;
    if (i < NN) g_deg[i] = 0;
}

// ---------------- 2) degree count -------------------------------------------
__global__ void k_deg(const int* __restrict__ ei) {
    int i = blockIdx.x * blockDim.x + threadIdx.x;   // NE/256 exact
    atomicAdd(&g_deg[ei[NE + i]], 1);
}

// ---------------- 3) scan phase 1 --------------------------------------------
__global__ __launch_bounds__(SCAN_B) void k_scan1() {
    int i = blockIdx.x * SCAN_B + threadIdx.x;
    int v = (i < NN) ? g_deg[i] : 0;
    int lane = threadIdx.x & 31, w = threadIdx.x >> 5;
    int s = v;
    #pragma unroll
    for (int o = 1; o < 32; o <<= 1) {
        int t = __shfl_up_sync(0xffffffffu, s, o);
        if (lane >= o) s += t;
    }
    __shared__ int wsum[32];
    if (lane == 31) wsum[w] = s;
    __syncthreads();
    if (w == 0) {
        int ws = wsum[lane];
        #pragma unroll
        for (int o = 1; o < 32; o <<= 1) {
            int t = __shfl_up_sync(0xffffffffu, ws, o);
            if (lane >= o) ws += t;
        }
        wsum[lane] = ws;
    }
    __syncthreads();
    int excl = s - v + (w > 0 ? wsum[w - 1] : 0);
    if (i < NN) g_loc[i] = excl;
    if (threadIdx.x == 0) g_bsum[blockIdx.x] = wsum[31];
}

// ---------------- 4) scan phase 2 --------------------------------------------
__global__ void k_scan2() {
    int i = threadIdx.x;                 // 128 threads
    int v = (i < NBLK) ? g_bsum[i] : 0;
    int lane = i & 31, w = i >> 5;
    int s = v;
    #pragma unroll
    for (int o = 1; o < 32; o <<= 1) {
        int t = __shfl_up_sync(0xffffffffu, s, o);
        if (lane >= o) s += t;
    }
    __shared__ int ws[4];
    if (lane == 31) ws[w] = s;
    __syncthreads();
    int add = 0;
    for (int k = 0; k < w; k++) add += ws[k];
    if (i < NBLK) g_bsumex[i] = s - v + add;
}

// ---------------- 5) scan phase 3 --------------------------------------------
__global__ void k_scan3() {
    int i = blockIdx.x * blockDim.x + threadIdx.x;
    if (i >= NN) return;
    int rp = g_loc[i] + g_bsumex[i >> 10];
    g_rowptr[i] = rp;
    g_fill[i]   = rp;
    g_inv[i]    = rsqrtf((float)g_deg[i] + 1.0f);
}

// ---------------- 6) CSR fill -------------------------------------------------
__global__ void k_fill(const int* __restrict__ ei) {
    int e = blockIdx.x * blockDim.x + threadIdx.x;   // NE/256 exact
    int s = ei[e];
    int d = ei[NE + e];
    int pos = atomicAdd(&g_fill[d], 1);
    float nm = g_inv[s] * g_inv[d];
    g_csr[pos] = make_int2(s, __float_as_int(nm));
}

// ---------------- 7) layer-1 gather: warp per node -----------------------------
__global__ __launch_bounds__(256) void k_gather1(const float* __restrict__ x) {
    int node = (blockIdx.x * 256 + threadIdx.x) >> 5;
    int lane = threadIdx.x & 31;
    int start = g_rowptr[node];
    int deg   = g_deg[node];
    float4 acc = make_float4(0.f, 0.f, 0.f, 0.f);
    int j = lane;
    for (; j + 32 < deg; j += 64) {
        int2 e0 = g_csr[start + j];
        int2 e1 = g_csr[start + j + 32];
        float4 x0 = reinterpret_cast<const float4*>(x)[e0.x];
        float4 x1 = reinterpret_cast<const float4*>(x)[e1.x];
        float n0 = __int_as_float(e0.y), n1 = __int_as_float(e1.y);
        acc.x = fmaf(x0.x, n0, acc.x); acc.y = fmaf(x0.y, n0, acc.y);
        acc.z = fmaf(x0.z, n0, acc.z); acc.w = fmaf(x0.w, n0, acc.w);
        acc.x = fmaf(x1.x, n1, acc.x); acc.y = fmaf(x1.y, n1, acc.y);
        acc.z = fmaf(x1.z, n1, acc.z); acc.w = fmaf(x1.w, n1, acc.w);
    }
    if (j < deg) {
        int2 e0 = g_csr[start + j];
        float4 x0 = reinterpret_cast<const float4*>(x)[e0.x];
        float n0 = __int_as_float(e0.y);
        acc.x = fmaf(x0.x, n0, acc.x); acc.y = fmaf(x0.y, n0, acc.y);
        acc.z = fmaf(x0.z, n0, acc.z); acc.w = fmaf(x0.w, n0, acc.w);
    }
    #pragma unroll
    for (int o = 16; o >= 1; o >>= 1) {
        acc.x += __shfl_xor_sync(0xffffffffu, acc.x, o);
        acc.y += __shfl_xor_sync(0xffffffffu, acc.y, o);
        acc.z += __shfl_xor_sync(0xffffffffu, acc.z, o);
        acc.w += __shfl_xor_sync(0xffffffffu, acc.w, o);
    }
    if (lane == 0) reinterpret_cast<float4*>(g_agg1)[node] = acc;
}

// ---------------- 8) fused dense: hW2 = (relu(agg@W1+b1))@W2 -------------------
__global__ __launch_bounds__(128) void k_layer12(const float* __restrict__ x,
                                                 const float* __restrict__ W1,
                                                 const float* __restrict__ b1,
                                                 const float* __restrict__ W2) {
    __shared__ float sW2[128 * 64];        // 32 KB
    __shared__ float sh[4][4][128];        // 8 KB

    int tid  = threadIdx.x;
    int lane = tid & 31;
    int w    = tid >> 5;
    int k0   = lane * 4;

    for (int i = tid; i < 128 * 64; i += 128) sW2[i] = W2[i];

    float rW1[4][4], rb1[4];
    #pragma unroll
    for (int c = 0; c < 4; c++)
        #pragma unroll
        for (int u = 0; u < 4; u++) rW1[c][u] = W1[c * 128 + k0 + u];
    #pragma unroll
    for (int u = 0; u < 4; u++) rb1[u] = b1[k0 + u];
    __syncthreads();

    for (int it = 0; it < 4; it++) {
        int nb = blockIdx.x * 64 + it * 16 + w * 4;

        #pragma unroll
        for (int n = 0; n < 4; n++) {
            int node = nb + n;
            if (node < NN) {
                float inv = g_inv[node];
                float i2  = inv * inv;
                float4 a  = reinterpret_cast<const float4*>(g_agg1)[node];
                float4 xv = reinterpret_cast<const float4*>(x)[node];
                a.x = fmaf(xv.x, i2, a.x);
                a.y = fmaf(xv.y, i2, a.y);
                a.z = fmaf(xv.z, i2, a.z);
                a.w = fmaf(xv.w, i2, a.w);
                float4 hv;
                float* hp = &hv.x;
                #pragma unroll
                for (int u = 0; u < 4; u++) {
                    float h = rb1[u];
                    h = fmaf(a.x, rW1[0][u], h);
                    h = fmaf(a.y, rW1[1][u], h);
                    h = fmaf(a.z, rW1[2][u], h);
                    h = fmaf(a.w, rW1[3][u], h);
                    hp[u] = fmaxf(h, 0.0f);
                }
                *reinterpret_cast<float4*>(&sh[w][n][k0]) = hv;
            }
        }
        __syncwarp();

        float acc[4][2];
        #pragma unroll
        for (int n = 0; n < 4; n++) { acc[n][0] = 0.f; acc[n][1] = 0.f; }

        #pragma unroll 16
        for (int k = 0; k < 128; k++) {
            float w0 = sW2[k * 64 + lane];
            float w1 = sW2[k * 64 + lane + 32];
            #pragma unroll
            for (int n = 0; n < 4; n++) {
                float hk = sh[w][n][k];
                acc[n][0] = fmaf(hk, w0, acc[n][0]);
                acc[n][1] = fmaf(hk, w1, acc[n][1]);
            }
        }

        #pragma unroll
        for (int n = 0; n < 4; n++) {
            int node = nb + n;
            if (node < NN) {
                g_hW2[node * 64 + lane]       = acc[n][0];
                g_hW2[node * 64 + lane + 32]  = acc[n][1];
                g_hW2h[node * 64 + lane]      = __float2half_rn(acc[n][0]);
                g_hW2h[node * 64 + lane + 32] = __float2half_rn(acc[n][1]);
            }
        }
        __syncwarp();
    }
}

// ---------------- 9) layer-2 gather (fp16 rows) fused with finalize ------------
__device__ __forceinline__ void fma_half4(float4& acc, unsigned lo, unsigned hi, float nm) {
    __half2 h0 = *reinterpret_cast<__half2*>(&lo);
    __half2 h1 = *reinterpret_cast<__half2*>(&hi);
    float2 f0 = __half22float2(h0);
    float2 f1 = __half22float2(h1);
    acc.x = fmaf(f0.x, nm, acc.x);
    acc.y = fmaf(f0.y, nm, acc.y);
    acc.z = fmaf(f1.x, nm, acc.z);
    acc.w = fmaf(f1.y, nm, acc.w);
}

__global__ __launch_bounds__(256) void k_gather2z(const float* __restrict__ b2) {
    unsigned t = blockIdx.x * 256u + threadIdx.x;   // NN*16 threads
    int node = t >> 4;
    int c    = t & 15;
    int start = g_rowptr[node];
    int deg   = g_deg[node];
    float inv = g_inv[node];
    float i2  = inv * inv;

    // self term (fp32)
    float4 self = reinterpret_cast<const float4*>(g_hW2)[node * 16 + c];
    float4 acc;
    acc.x = self.x * i2; acc.y = self.y * i2;
    acc.z = self.z * i2; acc.w = self.w * i2;

    const uint2* hrows = reinterpret_cast<const uint2*>(g_hW2h);

    int j = 0;
    for (; j + 1 < deg; j += 2) {
        int2 e0 = g_csr[start + j];
        int2 e1 = g_csr[start + j + 1];
        uint2 v0 = hrows[e0.x * 16 + c];
        uint2 v1 = hrows[e1.x * 16 + c];
        fma_half4(acc, v0.x, v0.y, __int_as_float(e0.y));
        fma_half4(acc, v1.x, v1.y, __int_as_float(e1.y));
    }
    if (j < deg) {
        int2 e0 = g_csr[start + j];
        uint2 v0 = hrows[e0.x * 16 + c];
        fma_half4(acc, v0.x, v0.y, __int_as_float(e0.y));
    }

    float4 bb = reinterpret_cast<const float4*>(b2)[c];
    acc.x += bb.x; acc.y += bb.y; acc.z += bb.z; acc.w += bb.w;
    reinterpret_cast<float4*>(g_z)[t] = acc;
}

// ---------------- 10) decode ----------------------------------------------------
__global__ __launch_bounds__(256) void k_decode(const int* __restrict__ eli,
                                                float* __restrict__ out) {
    unsigned t = blockIdx.x * 256u + threadIdx.x;   // NL*16 threads
    int e = t >> 4;
    int c = t & 15;
    int a = eli[e];
    int b = eli[NL + e];
    float4 za = reinterpret_cast<const float4*>(g_z)[a * 16 + c];
    float4 zb = reinterpret_cast<const float4*>(g_z)[b * 16 + c];
    float p = za.x * zb.x + za.y * zb.y + za.z * zb.z + za.w * zb.w;
    #pragma unroll
    for (int o = 8; o >= 1; o >>= 1) p += __shfl_xor_sync(0xffffffffu, p, o);
    if (c == 0) out[e] = p;
}

// ---------------- launch ---------------------------------------------------------
extern "C" void kernel_launch(void* const* d_in, const int* in_sizes, int n_in,
                              void* d_out, int out_size) {
    const float* x   = (const float*)d_in[0];
    const int*   ei  = (const int*)  d_in[1];
    const int*   eli = (const int*)  d_in[2];
    const float* W1  = (const float*)d_in[3];
    const float* b1  = (const float*)d_in[4];
    const float* W2  = (const float*)d_in[5];
    const float* b2  = (const float*)d_in[6];
    float* out = (float*)d_out;

    k_zero    <<<(NN + 255) / 256, 256>>>();
    k_deg     <<<NE / 256, 256>>>(ei);
    k_scan1   <<<NBLK, SCAN_B>>>();
    k_scan2   <<<1, 128>>>();
    k_scan3   <<<(NN + 255) / 256, 256>>>();
    k_fill    <<<NE / 256, 256>>>(ei);
    k_gather1 <<<NN * 32 / 256, 256>>>(x);
    k_layer12 <<<(NN + 63) / 64, 128>>>(x, W1, b1, W2);
    k_gather2z<<<NN * 16 / 256, 256>>>(b2);
    k_decode  <<<NL * 16 / 256, 256>>>(eli, out);
}

// round 4
// speedup vs baseline: 1.5796x; 1.0686x over previous
#include <cuda_runtime.h>
#include <cuda_fp16.h>

#define NN 100000
#define NE 3200000
#define NL 200000
#define SCAN_B 1024
#define NBLK ((NN + SCAN_B - 1) / SCAN_B)   // 98

// ---------------- scratch (device globals) ----------------------------------
__device__ int                  g_deg[NN];
__device__ float                g_inv[NN];
__device__ int                  g_loc[NN];
__device__ int                  g_bsum[NBLK];
__device__ int                  g_rowptr[NN];
__device__ int                  g_fill[NN];
__device__ int                  g_csr[NE];          // src only, dst-grouped
__device__ __align__(16) float  g_xs[NN * 4];       // x * inv[s]
__device__ __align__(16) float  g_agg1[NN * 4];     // normalized neighbor agg of x
__device__ __align__(16) float  g_hW2[NN * 64];     // fp32, UNscaled (self term)
__device__ __align__(16) __half2 g_hW2h[NN * 32];   // fp16, scaled by inv[s]
__device__ __align__(16) __half g_zh[NN * 64];      // fp16 z (decode table)

// ---------------- 1) zero degree --------------------------------------------
__global__ void k_zero() {
    int i = blockIdx.x * blockDim.x + threadIdx.x;
    if (i < NN) g_deg[i] = 0;
}

// ---------------- 2) degree count (int4 reads) -------------------------------
__global__ void k_deg(const int* __restrict__ ei) {
    int i = blockIdx.x * blockDim.x + threadIdx.x;   // NE/4 threads
    int4 d = reinterpret_cast<const int4*>(ei)[NE / 4 + i];
    atomicAdd(&g_deg[d.x], 1);
    atomicAdd(&g_deg[d.y], 1);
    atomicAdd(&g_deg[d.z], 1);
    atomicAdd(&g_deg[d.w], 1);
}

// ---------------- 3) scan phase 1: per-block scan ----------------------------
__global__ __launch_bounds__(SCAN_B) void k_scan1() {
    int i = blockIdx.x * SCAN_B + threadIdx.x;
    int v = (i < NN) ? g_deg[i] : 0;
    int lane = threadIdx.x & 31, w = threadIdx.x >> 5;
    int s = v;
    #pragma unroll
    for (int o = 1; o < 32; o <<= 1) {
        int t = __shfl_up_sync(0xffffffffu, s, o);
        if (lane >= o) s += t;
    }
    __shared__ int wsum[32];
    if (lane == 31) wsum[w] = s;
    __syncthreads();
    if (w == 0) {
        int ws = wsum[lane];
        #pragma unroll
        for (int o = 1; o < 32; o <<= 1) {
            int t = __shfl_up_sync(0xffffffffu, ws, o);
            if (lane >= o) ws += t;
        }
        wsum[lane] = ws;
    }
    __syncthreads();
    int excl = s - v + (w > 0 ? wsum[w - 1] : 0);
    if (i < NN) g_loc[i] = excl;
    if (threadIdx.x == 0) g_bsum[blockIdx.x] = wsum[31];
}

// ---------------- 4) scan finalize + inv + scaled x ---------------------------
// Each 256-thread block redundantly reduces the <=98 block sums it needs.
__global__ __launch_bounds__(256) void k_scan3(const float* __restrict__ x) {
    __shared__ int sred[8];
    int t = threadIdx.x;
    int lane = t & 31, w = t >> 5;
    int k = (blockIdx.x * 256) >> 10;          // how many full scan-blocks precede us
    int v = (t < k && t < NBLK) ? g_bsum[t] : 0;
    #pragma unroll
    for (int o = 16; o >= 1; o >>= 1) v += __shfl_xor_sync(0xffffffffu, v, o);
    if (lane == 0) sred[w] = v;
    __syncthreads();
    if (t == 0) {
        int s = 0;
        #pragma unroll
        for (int q = 0; q < 8; q++) s += sred[q];
        sred[0] = s;
    }
    __syncthreads();
    int off = sred[0];

    int i = blockIdx.x * 256 + t;
    if (i < NN) {
        int rp = g_loc[i] + off;
        g_rowptr[i] = rp;
        g_fill[i]   = rp;
        float inv = rsqrtf((float)g_deg[i] + 1.0f);
        g_inv[i] = inv;
        float4 xv = reinterpret_cast<const float4*>(x)[i];
        xv.x *= inv; xv.y *= inv; xv.z *= inv; xv.w *= inv;
        reinterpret_cast<float4*>(g_xs)[i] = xv;
    }
}

// ---------------- 5) CSR fill (src only, x2 vector) ---------------------------
__global__ void k_fill(const int* __restrict__ ei) {
    int i = blockIdx.x * blockDim.x + threadIdx.x;   // NE/2 threads
    int2 s2 = reinterpret_cast<const int2*>(ei)[i];
    int2 d2 = reinterpret_cast<const int2*>(ei)[NE / 2 + i];
    int p0 = atomicAdd(&g_fill[d2.x], 1);
    g_csr[p0] = s2.x;
    int p1 = atomicAdd(&g_fill[d2.y], 1);
    g_csr[p1] = s2.y;
}

// ---------------- 6) layer-1 gather: warp per node -----------------------------
__global__ __launch_bounds__(256) void k_gather1() {
    int node = (blockIdx.x * 256 + threadIdx.x) >> 5;
    int lane = threadIdx.x & 31;
    int start = g_rowptr[node];
    int deg   = g_deg[node];
    float4 acc = make_float4(0.f, 0.f, 0.f, 0.f);
    int j = lane;
    for (; j + 32 < deg; j += 64) {
        int s0 = g_csr[start + j];
        int s1 = g_csr[start + j + 32];
        float4 x0 = reinterpret_cast<const float4*>(g_xs)[s0];
        float4 x1 = reinterpret_cast<const float4*>(g_xs)[s1];
        acc.x += x0.x + x1.x; acc.y += x0.y + x1.y;
        acc.z += x0.z + x1.z; acc.w += x0.w + x1.w;
    }
    if (j < deg) {
        int s0 = g_csr[start + j];
        float4 x0 = reinterpret_cast<const float4*>(g_xs)[s0];
        acc.x += x0.x; acc.y += x0.y; acc.z += x0.z; acc.w += x0.w;
    }
    #pragma unroll
    for (int o = 16; o >= 1; o >>= 1) {
        acc.x += __shfl_xor_sync(0xffffffffu, acc.x, o);
        acc.y += __shfl_xor_sync(0xffffffffu, acc.y, o);
        acc.z += __shfl_xor_sync(0xffffffffu, acc.z, o);
        acc.w += __shfl_xor_sync(0xffffffffu, acc.w, o);
    }
    if (lane == 0) {
        float inv = g_inv[node];
        acc.x *= inv; acc.y *= inv; acc.z *= inv; acc.w *= inv;
        reinterpret_cast<float4*>(g_agg1)[node] = acc;
    }
}

// ---------------- 7) fused dense: hW2 = (relu(agg@W1+b1))@W2 -------------------
// 128 threads = 4 warps, 4 nodes/warp/iter, 8 iters = 128 nodes/block.
__global__ __launch_bounds__(128) void k_layer12(const float* __restrict__ x,
                                                 const float* __restrict__ W1,
                                                 const float* __restrict__ b1,
                                                 const float* __restrict__ W2) {
    __shared__ float sW2[128 * 64];        // 32 KB
    __shared__ float sh[4][4][128];        // 8 KB

    int tid  = threadIdx.x;
    int lane = tid & 31;
    int w    = tid >> 5;
    int k0   = lane * 4;

    for (int i = tid; i < 128 * 64; i += 128) sW2[i] = W2[i];

    float rW1[4][4], rb1[4];
    #pragma unroll
    for (int c = 0; c < 4; c++)
        #pragma unroll
        for (int u = 0; u < 4; u++) rW1[c][u] = W1[c * 128 + k0 + u];
    #pragma unroll
    for (int u = 0; u < 4; u++) rb1[u] = b1[k0 + u];
    __syncthreads();

    for (int it = 0; it < 8; it++) {
        int nb = blockIdx.x * 128 + it * 16 + w * 4;
        float invs[4];

        #pragma unroll
        for (int n = 0; n < 4; n++) {
            int node = nb + n;
            if (node < NN) {
                float inv = g_inv[node];
                invs[n] = inv;
                float i2 = inv * inv;
                float4 a  = reinterpret_cast<const float4*>(g_agg1)[node];
                float4 xv = reinterpret_cast<const float4*>(x)[node];
                a.x = fmaf(xv.x, i2, a.x);
                a.y = fmaf(xv.y, i2, a.y);
                a.z = fmaf(xv.z, i2, a.z);
                a.w = fmaf(xv.w, i2, a.w);
                float4 hv;
                float* hp = &hv.x;
                #pragma unroll
                for (int u = 0; u < 4; u++) {
                    float h = rb1[u];
                    h = fmaf(a.x, rW1[0][u], h);
                    h = fmaf(a.y, rW1[1][u], h);
                    h = fmaf(a.z, rW1[2][u], h);
                    h = fmaf(a.w, rW1[3][u], h);
                    hp[u] = fmaxf(h, 0.0f);
                }
                *reinterpret_cast<float4*>(&sh[w][n][k0]) = hv;
            }
        }
        __syncwarp();

        float acc[4][2];
        #pragma unroll
        for (int n = 0; n < 4; n++) { acc[n][0] = 0.f; acc[n][1] = 0.f; }

        #pragma unroll 16
        for (int k = 0; k < 128; k++) {
            float2 w01 = *reinterpret_cast<const float2*>(&sW2[k * 64 + 2 * lane]);
            #pragma unroll
            for (int n = 0; n < 4; n++) {
                float hk = sh[w][n][k];
                acc[n][0] = fmaf(hk, w01.x, acc[n][0]);
                acc[n][1] = fmaf(hk, w01.y, acc[n][1]);
            }
        }

        #pragma unroll
        for (int n = 0; n < 4; n++) {
            int node = nb + n;
            if (node < NN) {
                // fp32 unscaled (cols 2*lane, 2*lane+1)
                float2 f2; f2.x = acc[n][0]; f2.y = acc[n][1];
                reinterpret_cast<float2*>(g_hW2)[node * 32 + lane] = f2;
                // fp16 scaled by inv[node]
                g_hW2h[node * 32 + lane] =
                    __floats2half2_rn(acc[n][0] * invs[n], acc[n][1] * invs[n]);
            }
        }
        __syncwarp();
    }
}

// ---------------- 8) layer-2 gather (pre-scaled fp16) + finalize ----------------
__device__ __forceinline__ void add_half4(float4& acc, unsigned lo, unsigned hi) {
    float2 f0 = __half22float2(*reinterpret_cast<__half2*>(&lo));
    float2 f1 = __half22float2(*reinterpret_cast<__half2*>(&hi));
    acc.x += f0.x; acc.y += f0.y; acc.z += f1.x; acc.w += f1.y;
}

__global__ __launch_bounds__(256) void k_gather2z(const float* __restrict__ b2) {
    unsigned t = blockIdx.x * 256u + threadIdx.x;   // NN*16 threads
    int node = t >> 4;
    int c    = t & 15;
    int start = g_rowptr[node];
    int deg   = g_deg[node];
    float inv = g_inv[node];
    float i2  = inv * inv;

    const uint2* hrows = reinterpret_cast<const uint2*>(g_hW2h);

    float4 nb = make_float4(0.f, 0.f, 0.f, 0.f);
    int j = 0;
    for (; j + 1 < deg; j += 2) {
        int s0 = g_csr[start + j];
        int s1 = g_csr[start + j + 1];
        uint2 v0 = hrows[s0 * 16 + c];
        uint2 v1 = hrows[s1 * 16 + c];
        add_half4(nb, v0.x, v0.y);
        add_half4(nb, v1.x, v1.y);
    }
    if (j < deg) {
        int s0 = g_csr[start + j];
        uint2 v0 = hrows[s0 * 16 + c];
        add_half4(nb, v0.x, v0.y);
    }

    float4 self = reinterpret_cast<const float4*>(g_hW2)[node * 16 + c];
    float4 bb   = reinterpret_cast<const float4*>(b2)[c];
    float4 z;
    z.x = fmaf(nb.x, inv, fmaf(self.x, i2, bb.x));
    z.y = fmaf(nb.y, inv, fmaf(self.y, i2, bb.y));
    z.z = fmaf(nb.z, inv, fmaf(self.z, i2, bb.z));
    z.w = fmaf(nb.w, inv, fmaf(self.w, i2, bb.w));

    uint2 zo;
    __half2 h0 = __floats2half2_rn(z.x, z.y);
    __half2 h1 = __floats2half2_rn(z.z, z.w);
    zo.x = *reinterpret_cast<unsigned*>(&h0);
    zo.y = *reinterpret_cast<unsigned*>(&h1);
    reinterpret_cast<uint2*>(g_zh)[t] = zo;
}

// ---------------- 9) decode (fp16 z) --------------------------------------------
__global__ __launch_bounds__(256) void k_decode(const int* __restrict__ eli,
                                                float* __restrict__ out) {
    unsigned t = blockIdx.x * 256u + threadIdx.x;   // NL*16 threads
    int e = t >> 4;
    int c = t & 15;
    int a = eli[e];
    int b = eli[NL + e];
    const uint2* zr = reinterpret_cast<const uint2*>(g_zh);
    uint2 va = zr[a * 16 + c];
    uint2 vb = zr[b * 16 + c];
    float2 a0 = __half22float2(*reinterpret_cast<__half2*>(&va.x));
    float2 a1 = __half22float2(*reinterpret_cast<__half2*>(&va.y));
    float2 b0 = __half22float2(*reinterpret_cast<__half2*>(&vb.x));
    float2 b1 = __half22float2(*reinterpret_cast<__half2*>(&vb.y));
    float p = a0.x * b0.x + a0.y * b0.y + a1.x * b1.x + a1.y * b1.y;
    #pragma unroll
    for (int o = 8; o >= 1; o >>= 1) p += __shfl_xor_sync(0xffffffffu, p, o);
    if (c == 0) out[e] = p;
}

// ---------------- launch ----------------------------------------------------------
extern "C" void kernel_launch(void* const* d_in, const int* in_sizes, int n_in,
                              void* d_out, int out_size) {
    const float* x   = (const float*)d_in[0];
    const int*   ei  = (const int*)  d_in[1];
    const int*   eli = (const int*)  d_in[2];
    const float* W1  = (const float*)d_in[3];
    const float* b1  = (const float*)d_in[4];
    const float* W2  = (const float*)d_in[5];
    const float* b2  = (const float*)d_in[6];
    float* out = (float*)d_out;

    k_zero    <<<(NN + 255) / 256, 256>>>();
    k_deg     <<<NE / 4 / 256, 256>>>(ei);
    k_scan1   <<<NBLK, SCAN_B>>>();
    k_scan3   <<<(NN + 255) / 256, 256>>>(x);
    k_fill    <<<NE / 2 / 256, 256>>>(ei);
    k_gather1 <<<NN * 32 / 256, 256>>>();
    k_layer12 <<<(NN + 127) / 128, 128>>>(x, W1, b1, W2);
    k_gather2z<<<NN * 16 / 256, 256>>>(b2);
    k_decode  <<<NL * 16 / 256, 256>>>(eli, out);
}

// round 5
// speedup vs baseline: 1.6267x; 1.0298x over previous
#include <cuda_runtime.h>
#include <cuda_fp16.h>

#define NN 100000
#define NE 3200000
#define NL 200000
#define SCAN_B 1024
#define NBLK ((NN + SCAN_B - 1) / SCAN_B)   // 98

// ---------------- scratch (device globals) ----------------------------------
__device__ int                  g_deg[NN];      // zero-init at load; re-zeroed by k_decode
__device__ float                g_inv[NN];
__device__ int                  g_loc[NN];
__device__ int                  g_bsum[NBLK];
__device__ int                  g_rowptr[NN];
__device__ int                  g_fill[NN];
__device__ int                  g_csr[NE];          // src only, dst-grouped
__device__ __align__(16) float  g_xs[NN * 4];       // x * inv[s]
__device__ __align__(16) float  g_agg1[NN * 4];
__device__ __align__(16) float  g_hW2[NN * 64];     // fp32, UNscaled (self term)
__device__ __align__(16) __half2 g_hW2h[NN * 32];   // fp16, scaled by inv[s]
__device__ __align__(16) __half g_zh[NN * 64];      // fp16 z (decode table)

// ---------------- 1) degree count (int4 reads, 4 edges/thread) ---------------
__global__ void k_deg(const int* __restrict__ ei) {
    int i = blockIdx.x * blockDim.x + threadIdx.x;   // NE/4 threads
    int4 d = reinterpret_cast<const int4*>(ei)[NE / 4 + i];
    atomicAdd(&g_deg[d.x], 1);
    atomicAdd(&g_deg[d.y], 1);
    atomicAdd(&g_deg[d.z], 1);
    atomicAdd(&g_deg[d.w], 1);
}

// ---------------- 2) scan phase 1: per-block scan ----------------------------
__global__ __launch_bounds__(SCAN_B) void k_scan1() {
    int i = blockIdx.x * SCAN_B + threadIdx.x;
    int v = (i < NN) ? g_deg[i] : 0;
    int lane = threadIdx.x & 31, w = threadIdx.x >> 5;
    int s = v;
    #pragma unroll
    for (int o = 1; o < 32; o <<= 1) {
        int t = __shfl_up_sync(0xffffffffu, s, o);
        if (lane >= o) s += t;
    }
    __shared__ int wsum[32];
    if (lane == 31) wsum[w] = s;
    __syncthreads();
    if (w == 0) {
        int ws = wsum[lane];
        #pragma unroll
        for (int o = 1; o < 32; o <<= 1) {
            int t = __shfl_up_sync(0xffffffffu, ws, o);
            if (lane >= o) ws += t;
        }
        wsum[lane] = ws;
    }
    __syncthreads();
    int excl = s - v + (w > 0 ? wsum[w - 1] : 0);
    if (i < NN) g_loc[i] = excl;
    if (threadIdx.x == 0) g_bsum[blockIdx.x] = wsum[31];
}

// ---------------- 3) scan finalize + inv + scaled x ---------------------------
__global__ __launch_bounds__(256) void k_scan3(const float* __restrict__ x) {
    __shared__ int sred[8];
    int t = threadIdx.x;
    int lane = t & 31, w = t >> 5;
    int k = (blockIdx.x * 256) >> 10;
    int v = (t < k && t < NBLK) ? g_bsum[t] : 0;
    #pragma unroll
    for (int o = 16; o >= 1; o >>= 1) v += __shfl_xor_sync(0xffffffffu, v, o);
    if (lane == 0) sred[w] = v;
    __syncthreads();
    if (t == 0) {
        int s = 0;
        #pragma unroll
        for (int q = 0; q < 8; q++) s += sred[q];
        sred[0] = s;
    }
    __syncthreads();
    int off = sred[0];

    int i = blockIdx.x * 256 + t;
    if (i < NN) {
        int rp = g_loc[i] + off;
        g_rowptr[i] = rp;
        g_fill[i]   = rp;
        float inv = rsqrtf((float)g_deg[i] + 1.0f);
        g_inv[i] = inv;
        float4 xv = reinterpret_cast<const float4*>(x)[i];
        xv.x *= inv; xv.y *= inv; xv.z *= inv; xv.w *= inv;
        reinterpret_cast<float4*>(g_xs)[i] = xv;
    }
}

// ---------------- 4) CSR fill (4 edges/thread, int4 loads) --------------------
__global__ void k_fill(const int* __restrict__ ei) {
    int i = blockIdx.x * blockDim.x + threadIdx.x;   // NE/4 threads
    int4 s4 = reinterpret_cast<const int4*>(ei)[i];
    int4 d4 = reinterpret_cast<const int4*>(ei)[NE / 4 + i];
    int p0 = atomicAdd(&g_fill[d4.x], 1); g_csr[p0] = s4.x;
    int p1 = atomicAdd(&g_fill[d4.y], 1); g_csr[p1] = s4.y;
    int p2 = atomicAdd(&g_fill[d4.z], 1); g_csr[p2] = s4.z;
    int p3 = atomicAdd(&g_fill[d4.w], 1); g_csr[p3] = s4.w;
}

// ---------------- 5) layer-1 gather: warp per node -----------------------------
__global__ __launch_bounds__(256) void k_gather1() {
    int node = (blockIdx.x * 256 + threadIdx.x) >> 5;
    int lane = threadIdx.x & 31;
    int start = g_rowptr[node];
    int deg   = g_deg[node];
    float4 acc = make_float4(0.f, 0.f, 0.f, 0.f);
    int j = lane;
    for (; j + 32 < deg; j += 64) {
        int s0 = g_csr[start + j];
        int s1 = g_csr[start + j + 32];
        float4 x0 = reinterpret_cast<const float4*>(g_xs)[s0];
        float4 x1 = reinterpret_cast<const float4*>(g_xs)[s1];
        acc.x += x0.x + x1.x; acc.y += x0.y + x1.y;
        acc.z += x0.z + x1.z; acc.w += x0.w + x1.w;
    }
    if (j < deg) {
        int s0 = g_csr[start + j];
        float4 x0 = reinterpret_cast<const float4*>(g_xs)[s0];
        acc.x += x0.x; acc.y += x0.y; acc.z += x0.z; acc.w += x0.w;
    }
    #pragma unroll
    for (int o = 16; o >= 1; o >>= 1) {
        acc.x += __shfl_xor_sync(0xffffffffu, acc.x, o);
        acc.y += __shfl_xor_sync(0xffffffffu, acc.y, o);
        acc.z += __shfl_xor_sync(0xffffffffu, acc.z, o);
        acc.w += __shfl_xor_sync(0xffffffffu, acc.w, o);
    }
    if (lane == 0) {
        float inv = g_inv[node];
        acc.x *= inv; acc.y *= inv; acc.z *= inv; acc.w *= inv;
        reinterpret_cast<float4*>(g_agg1)[node] = acc;
    }
}

// ---------------- 6) fused dense: hW2 = (relu(agg@W1+b1))@W2 -------------------
__global__ __launch_bounds__(128) void k_layer12(const float* __restrict__ x,
                                                 const float* __restrict__ W1,
                                                 const float* __restrict__ b1,
                                                 const float* __restrict__ W2) {
    __shared__ float sW2[128 * 64];
    __shared__ float sh[4][4][128];

    int tid  = threadIdx.x;
    int lane = tid & 31;
    int w    = tid >> 5;
    int k0   = lane * 4;

    for (int i = tid; i < 128 * 64; i += 128) sW2[i] = W2[i];

    float rW1[4][4], rb1[4];
    #pragma unroll
    for (int c = 0; c < 4; c++)
        #pragma unroll
        for (int u = 0; u < 4; u++) rW1[c][u] = W1[c * 128 + k0 + u];
    #pragma unroll
    for (int u = 0; u < 4; u++) rb1[u] = b1[k0 + u];
    __syncthreads();

    for (int it = 0; it < 8; it++) {
        int nb = blockIdx.x * 128 + it * 16 + w * 4;
        float invs[4];

        #pragma unroll
        for (int n = 0; n < 4; n++) {
            int node = nb + n;
            if (node < NN) {
                float inv = g_inv[node];
                invs[n] = inv;
                float i2 = inv * inv;
                float4 a  = reinterpret_cast<const float4*>(g_agg1)[node];
                float4 xv = reinterpret_cast<const float4*>(x)[node];
                a.x = fmaf(xv.x, i2, a.x);
                a.y = fmaf(xv.y, i2, a.y);
                a.z = fmaf(xv.z, i2, a.z);
                a.w = fmaf(xv.w, i2, a.w);
                float4 hv;
                float* hp = &hv.x;
                #pragma unroll
                for (int u = 0; u < 4; u++) {
                    float h = rb1[u];
                    h = fmaf(a.x, rW1[0][u], h);
                    h = fmaf(a.y, rW1[1][u], h);
                    h = fmaf(a.z, rW1[2][u], h);
                    h = fmaf(a.w, rW1[3][u], h);
                    hp[u] = fmaxf(h, 0.0f);
                }
                *reinterpret_cast<float4*>(&sh[w][n][k0]) = hv;
            }
        }
        __syncwarp();

        float acc[4][2];
        #pragma unroll
        for (int n = 0; n < 4; n++) { acc[n][0] = 0.f; acc[n][1] = 0.f; }

        #pragma unroll 16
        for (int k = 0; k < 128; k++) {
            float2 w01 = *reinterpret_cast<const float2*>(&sW2[k * 64 + 2 * lane]);
            #pragma unroll
            for (int n = 0; n < 4; n++) {
                float hk = sh[w][n][k];
                acc[n][0] = fmaf(hk, w01.x, acc[n][0]);
                acc[n][1] = fmaf(hk, w01.y, acc[n][1]);
            }
        }

        #pragma unroll
        for (int n = 0; n < 4; n++) {
            int node = nb + n;
            if (node < NN) {
                float2 f2; f2.x = acc[n][0]; f2.y = acc[n][1];
                reinterpret_cast<float2*>(g_hW2)[node * 32 + lane] = f2;
                g_hW2h[node * 32 + lane] =
                    __floats2half2_rn(acc[n][0] * invs[n], acc[n][1] * invs[n]);
            }
        }
        __syncwarp();
    }
}

// ---------------- 7) layer-2 gather (8 lanes/node, uint4 rows) -----------------
__device__ __forceinline__ void add_h8(float* a, const uint4& v) {
    float2 f0 = __half22float2(*reinterpret_cast<const __half2*>(&v.x));
    float2 f1 = __half22float2(*reinterpret_cast<const __half2*>(&v.y));
    float2 f2 = __half22float2(*reinterpret_cast<const __half2*>(&v.z));
    float2 f3 = __half22float2(*reinterpret_cast<const __half2*>(&v.w));
    a[0] += f0.x; a[1] += f0.y; a[2] += f1.x; a[3] += f1.y;
    a[4] += f2.x; a[5] += f2.y; a[6] += f3.x; a[7] += f3.y;
}

__global__ __launch_bounds__(256) void k_gather2z(const float* __restrict__ b2) {
    unsigned t = blockIdx.x * 256u + threadIdx.x;   // NN*8 threads
    int node = t >> 3;
    int c    = t & 7;
    int start = g_rowptr[node];
    int deg   = g_deg[node];
    float inv = g_inv[node];
    float i2  = inv * inv;

    const uint4* hrows = reinterpret_cast<const uint4*>(g_hW2h);  // 8 uint4 per row

    float acc[8] = {0.f, 0.f, 0.f, 0.f, 0.f, 0.f, 0.f, 0.f};
    int j = 0;
    for (; j + 1 < deg; j += 2) {
        int s0 = g_csr[start + j];
        int s1 = g_csr[start + j + 1];
        uint4 v0 = hrows[s0 * 8 + c];
        uint4 v1 = hrows[s1 * 8 + c];
        add_h8(acc, v0);
        add_h8(acc, v1);
    }
    if (j < deg) {
        int s0 = g_csr[start + j];
        uint4 v0 = hrows[s0 * 8 + c];
        add_h8(acc, v0);
    }

    float4 sf0 = reinterpret_cast<const float4*>(g_hW2)[node * 16 + 2 * c];
    float4 sf1 = reinterpret_cast<const float4*>(g_hW2)[node * 16 + 2 * c + 1];
    float4 bb0 = reinterpret_cast<const float4*>(b2)[2 * c];
    float4 bb1 = reinterpret_cast<const float4*>(b2)[2 * c + 1];

    float z0 = fmaf(acc[0], inv, fmaf(sf0.x, i2, bb0.x));
    float z1 = fmaf(acc[1], inv, fmaf(sf0.y, i2, bb0.y));
    float z2 = fmaf(acc[2], inv, fmaf(sf0.z, i2, bb0.z));
    float z3 = fmaf(acc[3], inv, fmaf(sf0.w, i2, bb0.w));
    float z4 = fmaf(acc[4], inv, fmaf(sf1.x, i2, bb1.x));
    float z5 = fmaf(acc[5], inv, fmaf(sf1.y, i2, bb1.y));
    float z6 = fmaf(acc[6], inv, fmaf(sf1.z, i2, bb1.z));
    float z7 = fmaf(acc[7], inv, fmaf(sf1.w, i2, bb1.w));

    uint4 zo;
    __half2 h0 = __floats2half2_rn(z0, z1);
    __half2 h1 = __floats2half2_rn(z2, z3);
    __half2 h2 = __floats2half2_rn(z4, z5);
    __half2 h3 = __floats2half2_rn(z6, z7);
    zo.x = *reinterpret_cast<unsigned*>(&h0);
    zo.y = *reinterpret_cast<unsigned*>(&h1);
    zo.z = *reinterpret_cast<unsigned*>(&h2);
    zo.w = *reinterpret_cast<unsigned*>(&h3);
    reinterpret_cast<uint4*>(g_zh)[t] = zo;
}

// ---------------- 8) decode (8 lanes/edge, uint4) + re-zero g_deg ---------------
__global__ __launch_bounds__(256) void k_decode(const int* __restrict__ eli,
                                                float* __restrict__ out) {
    unsigned t = blockIdx.x * 256u + threadIdx.x;   // NL*8 threads
    int e = t >> 3;
    int c = t & 7;
    int a = eli[e];
    int b = eli[NL + e];
    const uint4* zr = reinterpret_cast<const uint4*>(g_zh);
    uint4 va = zr[a * 8 + c];
    uint4 vb = zr[b * 8 + c];
    float2 a0 = __half22float2(*reinterpret_cast<__half2*>(&va.x));
    float2 a1 = __half22float2(*reinterpret_cast<__half2*>(&va.y));
    float2 a2 = __half22float2(*reinterpret_cast<__half2*>(&va.z));
    float2 a3 = __half22float2(*reinterpret_cast<__half2*>(&va.w));
    float2 b0 = __half22float2(*reinterpret_cast<__half2*>(&vb.x));
    float2 b1 = __half22float2(*reinterpret_cast<__half2*>(&vb.y));
    float2 b2 = __half22float2(*reinterpret_cast<__half2*>(&vb.z));
    float2 b3 = __half22float2(*reinterpret_cast<__half2*>(&vb.w));
    float p = a0.x * b0.x + a0.y * b0.y + a1.x * b1.x + a1.y * b1.y
            + a2.x * b2.x + a2.y * b2.y + a3.x * b3.x + a3.y * b3.y;
    #pragma unroll
    for (int o = 4; o >= 1; o >>= 1) p += __shfl_xor_sync(0xffffffffu, p, o);
    if (c == 0) out[e] = p;
    if (t < NN) g_deg[t] = 0;     // restore precondition for the next replay
}

// ---------------- launch ----------------------------------------------------------
extern "C" void kernel_launch(void* const* d_in, const int* in_sizes, int n_in,
                              void* d_out, int out_size) {
    const float* x   = (const float*)d_in[0];
    const int*   ei  = (const int*)  d_in[1];
    const int*   eli = (const int*)  d_in[2];
    const float* W1  = (const float*)d_in[3];
    const float* b1  = (const float*)d_in[4];
    const float* W2  = (const float*)d_in[5];
    const float* b2  = (const float*)d_in[6];
    float* out = (float*)d_out;

    k_deg     <<<NE / 4 / 256, 256>>>(ei);
    k_scan1   <<<NBLK, SCAN_B>>>();
    k_scan3   <<<(NN + 255) / 256, 256>>>(x);
    k_fill    <<<NE / 4 / 256, 256>>>(ei);
    k_gather1 <<<NN * 32 / 256, 256>>>();
    k_layer12 <<<(NN + 127) / 128, 128>>>(x, W1, b1, W2);
    k_gather2z<<<NN * 8 / 256, 256>>>(b2);
    k_decode  <<<NL * 8 / 256, 256>>>(eli, out);
}

// round 7
// speedup vs baseline: 1.6883x; 1.0379x over previous
#include <cuda_runtime.h>
#include <cuda_fp16.h>

#define NN 100000
#define NE 3200000
#define NL 200000
#define SCAN_B 1024
#define NBLK ((NN + SCAN_B - 1) / SCAN_B)   // 98

// ---------------- scratch (device globals) ----------------------------------
__device__ int                  g_deg[NN];      // zero-init at load; re-zeroed by k_decode
__device__ float                g_inv[NN];
__device__ int                  g_loc[NN];
__device__ int                  g_bsum[NBLK];
__device__ int                  g_rowptr[NN];
__device__ int                  g_fill[NN];
__device__ int                  g_csr[NE];          // src only, dst-grouped
__device__ __align__(16) float  g_xs[NN * 4];       // x * inv[s]
__device__ __align__(16) float  g_agg1[NN * 4];
__device__ __align__(16) __half2 g_hW2h[NN * 32];   // fp16, scaled by inv[s]
__device__ __align__(16) __half g_zh[NN * 64];      // fp16 z (decode table)

// ---------------- 1) degree count (int4 reads, 4 edges/thread) ---------------
__global__ void k_deg(const int* __restrict__ ei) {
    int i = blockIdx.x * blockDim.x + threadIdx.x;   // NE/4 threads
    int4 d = reinterpret_cast<const int4*>(ei)[NE / 4 + i];
    atomicAdd(&g_deg[d.x], 1);
    atomicAdd(&g_deg[d.y], 1);
    atomicAdd(&g_deg[d.z], 1);
    atomicAdd(&g_deg[d.w], 1);
}

// ---------------- 2) scan phase 1: per-block scan ----------------------------
__global__ __launch_bounds__(SCAN_B) void k_scan1() {
    int i = blockIdx.x * SCAN_B + threadIdx.x;
    int v = (i < NN) ? g_deg[i] : 0;
    int lane = threadIdx.x & 31, w = threadIdx.x >> 5;
    int s = v;
    #pragma unroll
    for (int o = 1; o < 32; o <<= 1) {
        int t = __shfl_up_sync(0xffffffffu, s, o);
        if (lane >= o) s += t;
    }
    __shared__ int wsum[32];
    if (lane == 31) wsum[w] = s;
    __syncthreads();
    if (w == 0) {
        int ws = wsum[lane];
        #pragma unroll
        for (int o = 1; o < 32; o <<= 1) {
            int t = __shfl_up_sync(0xffffffffu, ws, o);
            if (lane >= o) ws += t;
        }
        wsum[lane] = ws;
    }
    __syncthreads();
    int excl = s - v + (w > 0 ? wsum[w - 1] : 0);
    if (i < NN) g_loc[i] = excl;
    if (threadIdx.x == 0) g_bsum[blockIdx.x] = wsum[31];
}

// ---------------- 3) scan finalize + inv + scaled x ---------------------------
__global__ __launch_bounds__(256) void k_scan3(const float* __restrict__ x) {
    __shared__ int sred[8];
    int t = threadIdx.x;
    int lane = t & 31, w = t >> 5;
    int k = (blockIdx.x * 256) >> 10;
    int v = (t < k && t < NBLK) ? g_bsum[t] : 0;
    #pragma unroll
    for (int o = 16; o >= 1; o >>= 1) v += __shfl_xor_sync(0xffffffffu, v, o);
    if (lane == 0) sred[w] = v;
    __syncthreads();
    if (t == 0) {
        int s = 0;
        #pragma unroll
        for (int q = 0; q < 8; q++) s += sred[q];
        sred[0] = s;
    }
    __syncthreads();
    int off = sred[0];

    int i = blockIdx.x * 256 + t;
    if (i < NN) {
        int rp = g_loc[i] + off;
        g_rowptr[i] = rp;
        g_fill[i]   = rp;
        float inv = rsqrtf((float)g_deg[i] + 1.0f);
        g_inv[i] = inv;
        float4 xv = reinterpret_cast<const float4*>(x)[i];
        xv.x *= inv; xv.y *= inv; xv.z *= inv; xv.w *= inv;
        reinterpret_cast<float4*>(g_xs)[i] = xv;
    }
}

// ---------------- 4) CSR fill (4 edges/thread, int4 loads) --------------------
__global__ void k_fill(const int* __restrict__ ei) {
    int i = blockIdx.x * blockDim.x + threadIdx.x;   // NE/4 threads
    int4 s4 = reinterpret_cast<const int4*>(ei)[i];
    int4 d4 = reinterpret_cast<const int4*>(ei)[NE / 4 + i];
    int p0 = atomicAdd(&g_fill[d4.x], 1); g_csr[p0] = s4.x;
    int p1 = atomicAdd(&g_fill[d4.y], 1); g_csr[p1] = s4.y;
    int p2 = atomicAdd(&g_fill[d4.z], 1); g_csr[p2] = s4.z;
    int p3 = atomicAdd(&g_fill[d4.w], 1); g_csr[p3] = s4.w;
}

// ---------------- 5) layer-1 gather: warp per node -----------------------------
__global__ __launch_bounds__(256) void k_gather1() {
    int node = (blockIdx.x * 256 + threadIdx.x) >> 5;
    int lane = threadIdx.x & 31;
    int start = g_rowptr[node];
    int deg   = g_deg[node];
    float4 acc = make_float4(0.f, 0.f, 0.f, 0.f);
    int j = lane;
    for (; j + 32 < deg; j += 64) {
        int s0 = g_csr[start + j];
        int s1 = g_csr[start + j + 32];
        float4 x0 = reinterpret_cast<const float4*>(g_xs)[s0];
        float4 x1 = reinterpret_cast<const float4*>(g_xs)[s1];
        acc.x += x0.x + x1.x; acc.y += x0.y + x1.y;
        acc.z += x0.z + x1.z; acc.w += x0.w + x1.w;
    }
    if (j < deg) {
        int s0 = g_csr[start + j];
        float4 x0 = reinterpret_cast<const float4*>(g_xs)[s0];
        acc.x += x0.x; acc.y += x0.y; acc.z += x0.z; acc.w += x0.w;
    }
    #pragma unroll
    for (int o = 16; o >= 1; o >>= 1) {
        acc.x += __shfl_xor_sync(0xffffffffu, acc.x, o);
        acc.y += __shfl_xor_sync(0xffffffffu, acc.y, o);
        acc.z += __shfl_xor_sync(0xffffffffu, acc.z, o);
        acc.w += __shfl_xor_sync(0xffffffffu, acc.w, o);
    }
    if (lane == 0) {
        float inv = g_inv[node];
        acc.x *= inv; acc.y *= inv; acc.z *= inv; acc.w *= inv;
        reinterpret_cast<float4*>(g_agg1)[node] = acc;
    }
}

// ---------------- 6) fused dense: hW2h = ((relu(agg@W1+b1))@W2)*inv ------------
// 128 threads = 4 warps, 4 nodes/warp/iter, 8 iters = 128 nodes/block.
__global__ __launch_bounds__(128) void k_layer12(const float* __restrict__ x,
                                                 const float* __restrict__ W1,
                                                 const float* __restrict__ b1,
                                                 const float* __restrict__ W2) {
    __shared__ float sW2[128 * 64];
    __shared__ float sh[4][4][128];

    int tid  = threadIdx.x;
    int lane = tid & 31;
    int w    = tid >> 5;
    int k0   = lane * 4;

    for (int i = tid; i < 128 * 64; i += 128) sW2[i] = W2[i];

    float rW1[4][4], rb1[4];
    #pragma unroll
    for (int c = 0; c < 4; c++)
        #pragma unroll
        for (int u = 0; u < 4; u++) rW1[c][u] = W1[c * 128 + k0 + u];
    #pragma unroll
    for (int u = 0; u < 4; u++) rb1[u] = b1[k0 + u];
    __syncthreads();

    for (int it = 0; it < 8; it++) {
        int nb = blockIdx.x * 128 + it * 16 + w * 4;
        float invs[4];

        #pragma unroll
        for (int n = 0; n < 4; n++) {
            int node = nb + n;
            if (node < NN) {
                float inv = g_inv[node];
                invs[n] = inv;
                float i2 = inv * inv;
                float4 a  = reinterpret_cast<const float4*>(g_agg1)[node];
                float4 xv = reinterpret_cast<const float4*>(x)[node];
                a.x = fmaf(xv.x, i2, a.x);
                a.y = fmaf(xv.y, i2, a.y);
                a.z = fmaf(xv.z, i2, a.z);
                a.w = fmaf(xv.w, i2, a.w);
                float4 hv;
                float* hp = &hv.x;
                #pragma unroll
                for (int u = 0; u < 4; u++) {
                    float h = rb1[u];
                    h = fmaf(a.x, rW1[0][u], h);
                    h = fmaf(a.y, rW1[1][u], h);
                    h = fmaf(a.z, rW1[2][u], h);
                    h = fmaf(a.w, rW1[3][u], h);
                    hp[u] = fmaxf(h, 0.0f);
                }
                *reinterpret_cast<float4*>(&sh[w][n][k0]) = hv;
            }
        }
        __syncwarp();

        float acc[4][2];
        #pragma unroll
        for (int n = 0; n < 4; n++) { acc[n][0] = 0.f; acc[n][1] = 0.f; }

        #pragma unroll 16
        for (int k = 0; k < 128; k++) {
            float2 w01 = *reinterpret_cast<const float2*>(&sW2[k * 64 + 2 * lane]);
            #pragma unroll
            for (int n = 0; n < 4; n++) {
                float hk = sh[w][n][k];
                acc[n][0] = fmaf(hk, w01.x, acc[n][0]);
                acc[n][1] = fmaf(hk, w01.y, acc[n][1]);
            }
        }

        #pragma unroll
        for (int n = 0; n < 4; n++) {
            int node = nb + n;
            if (node < NN) {
                g_hW2h[node * 32 + lane] =
                    __floats2half2_rn(acc[n][0] * invs[n], acc[n][1] * invs[n]);
            }
        }
        __syncwarp();
    }
}

// ---------------- 7) layer-2 gather (8 lanes/node, uint4 rows) -----------------
__device__ __forceinline__ void add_h8(float* a, const uint4& v) {
    float2 f0 = __half22float2(*reinterpret_cast<const __half2*>(&v.x));
    float2 f1 = __half22float2(*reinterpret_cast<const __half2*>(&v.y));
    float2 f2 = __half22float2(*reinterpret_cast<const __half2*>(&v.z));
    float2 f3 = __half22float2(*reinterpret_cast<const __half2*>(&v.w));
    a[0] += f0.x; a[1] += f0.y; a[2] += f1.x; a[3] += f1.y;
    a[4] += f2.x; a[5] += f2.y; a[6] += f3.x; a[7] += f3.y;
}

__global__ __launch_bounds__(256) void k_gather2z(const float* __restrict__ b2) {
    unsigned t = blockIdx.x * 256u + threadIdx.x;   // NN*8 threads
    int node = t >> 3;
    int c    = t & 7;
    int start = g_rowptr[node];
    int deg   = g_deg[node];
    float inv = g_inv[node];

    const uint4* hrows = reinterpret_cast<const uint4*>(g_hW2h);  // 8 uint4 per row

    // self term: hW2 * i2 == hW2h * inv (hW2h already scaled by inv)
    float acc[8] = {0.f, 0.f, 0.f, 0.f, 0.f, 0.f, 0.f, 0.f};
    add_h8(acc, hrows[node * 8 + c]);

    int j = 0;
    for (; j + 1 < deg; j += 2) {
        int s0 = g_csr[start + j];
        int s1 = g_csr[start + j + 1];
        uint4 v0 = hrows[s0 * 8 + c];
        uint4 v1 = hrows[s1 * 8 + c];
        add_h8(acc, v0);
        add_h8(acc, v1);
    }
    if (j < deg) {
        int s0 = g_csr[start + j];
        uint4 v0 = hrows[s0 * 8 + c];
        add_h8(acc, v0);
    }

    float4 bb0 = reinterpret_cast<const float4*>(b2)[2 * c];
    float4 bb1 = reinterpret_cast<const float4*>(b2)[2 * c + 1];
    float z0 = fmaf(acc[0], inv, bb0.x);
    float z1 = fmaf(acc[1], inv, bb0.y);
    float z2 = fmaf(acc[2], inv, bb0.z);
    float z3 = fmaf(acc[3], inv, bb0.w);
    float z4 = fmaf(acc[4], inv, bb1.x);
    float z5 = fmaf(acc[5], inv, bb1.y);
    float z6 = fmaf(acc[6], inv, bb1.z);
    float z7 = fmaf(acc[7], inv, bb1.w);

    uint4 zo;
    __half2 h0 = __floats2half2_rn(z0, z1);
    __half2 h1 = __floats2half2_rn(z2, z3);
    __half2 h2 = __floats2half2_rn(z4, z5);
    __half2 h3 = __floats2half2_rn(z6, z7);
    zo.x = *reinterpret_cast<unsigned*>(&h0);
    zo.y = *reinterpret_cast<unsigned*>(&h1);
    zo.z = *reinterpret_cast<unsigned*>(&h2);
    zo.w = *reinterpret_cast<unsigned*>(&h3);
    reinterpret_cast<uint4*>(g_zh)[t] = zo;
}

// ---------------- 8) decode (8 lanes/edge, uint4) + re-zero g_deg ---------------
__global__ __launch_bounds__(256) void k_decode(const int* __restrict__ eli,
                                                float* __restrict__ out) {
    unsigned t = blockIdx.x * 256u + threadIdx.x;   // NL*8 threads
    int e = t >> 3;
    int c = t & 7;
    int a = eli[e];
    int b = eli[NL + e];
    const uint4* zr = reinterpret_cast<const uint4*>(g_zh);
    uint4 va = zr[a * 8 + c];
    uint4 vb = zr[b * 8 + c];
    float2 a0 = __half22float2(*reinterpret_cast<__half2*>(&va.x));
    float2 a1 = __half22float2(*reinterpret_cast<__half2*>(&va.y));
    float2 a2 = __half22float2(*reinterpret_cast<__half2*>(&va.z));
    float2 a3 = __half22float2(*reinterpret_cast<__half2*>(&va.w));
    float2 b0 = __half22float2(*reinterpret_cast<__half2*>(&vb.x));
    float2 b1 = __half22float2(*reinterpret_cast<__half2*>(&vb.y));
    float2 b2 = __half22float2(*reinterpret_cast<__half2*>(&vb.z));
    float2 b3 = __half22float2(*reinterpret_cast<__half2*>(&vb.w));
    float p = a0.x * b0.x + a0.y * b0.y + a1.x * b1.x + a1.y * b1.y
            + a2.x * b2.x + a2.y * b2.y + a3.x * b3.x + a3.y * b3.y;
    #pragma unroll
    for (int o = 4; o >= 1; o >>= 1) p += __shfl_xor_sync(0xffffffffu, p, o);
    if (c == 0) out[e] = p;
    if (t < NN) g_deg[t] = 0;     // restore precondition for the next replay
}

// ---------------- launch ----------------------------------------------------------
extern "C" void kernel_launch(void* const* d_in, const int* in_sizes, int n_in,
                              void* d_out, int out_size) {
    const float* x   = (const float*)d_in[0];
    const int*   ei  = (const int*)  d_in[1];
    const int*   eli = (const int*)  d_in[2];
    const float* W1  = (const float*)d_in[3];
    const float* b1  = (const float*)d_in[4];
    const float* W2  = (const float*)d_in[5];
    const float* b2  = (const float*)d_in[6];
    float* out = (float*)d_out;

    k_deg     <<<NE / 4 / 256, 256>>>(ei);
    k_scan1   <<<NBLK, SCAN_B>>>();
    k_scan3   <<<(NN + 255) / 256, 256>>>(x);
    k_fill    <<<NE / 4 / 256, 256>>>(ei);
    k_gather1 <<<NN * 32 / 256, 256>>>();
    k_layer12 <<<(NN + 127) / 128, 128>>>(x, W1, b1, W2);
    k_gather2z<<<NN * 8 / 256, 256>>>(b2);
    k_decode  <<<NL * 8 / 256, 256>>>(eli, out);
}

// round 8
// speedup vs baseline: 2.0457x; 1.2117x over previous
#include <cuda_runtime.h>
#include <cuda_fp16.h>
#include <cstdint>

#define NN 100000
#define NE 3200000
#define NL 200000
#define SCAN_B 1024
#define NBLK ((NN + SCAN_B - 1) / SCAN_B)   // 98

// ---------------- scratch (device globals) ----------------------------------
__device__ int                  g_deg[NN];      // zero-init at load; re-zeroed by k_decode
__device__ float                g_inv[NN];
__device__ int                  g_loc[NN];
__device__ int                  g_bsum[NBLK];
__device__ int                  g_rowptr[NN];
__device__ int                  g_fill[NN];
__device__ int                  g_csr[NE];          // src only, dst-grouped
__device__ __align__(16) float  g_xs[NN * 4];       // x * inv[s]
__device__ __align__(16) float  g_agg1[NN * 4];
__device__ __align__(16) __half2 g_hW2h[NN * 32];   // fp16, scaled by inv[s]
__device__ __align__(16) __half g_zh[NN * 64];      // fp16 z (decode table)

// ---------------- 1) degree count (int4 reads, 4 edges/thread) ---------------
__global__ void k_deg(const int* __restrict__ ei) {
    int i = blockIdx.x * blockDim.x + threadIdx.x;   // NE/4 threads
    int4 d = reinterpret_cast<const int4*>(ei)[NE / 4 + i];
    atomicAdd(&g_deg[d.x], 1);
    atomicAdd(&g_deg[d.y], 1);
    atomicAdd(&g_deg[d.z], 1);
    atomicAdd(&g_deg[d.w], 1);
}

// ---------------- 2) scan phase 1: per-block scan ----------------------------
__global__ __launch_bounds__(SCAN_B) void k_scan1() {
    int i = blockIdx.x * SCAN_B + threadIdx.x;
    int v = (i < NN) ? g_deg[i] : 0;
    int lane = threadIdx.x & 31, w = threadIdx.x >> 5;
    int s = v;
    #pragma unroll
    for (int o = 1; o < 32; o <<= 1) {
        int t = __shfl_up_sync(0xffffffffu, s, o);
        if (lane >= o) s += t;
    }
    __shared__ int wsum[32];
    if (lane == 31) wsum[w] = s;
    __syncthreads();
    if (w == 0) {
        int ws = wsum[lane];
        #pragma unroll
        for (int o = 1; o < 32; o <<= 1) {
            int t = __shfl_up_sync(0xffffffffu, ws, o);
            if (lane >= o) ws += t;
        }
        wsum[lane] = ws;
    }
    __syncthreads();
    int excl = s - v + (w > 0 ? wsum[w - 1] : 0);
    if (i < NN) g_loc[i] = excl;
    if (threadIdx.x == 0) g_bsum[blockIdx.x] = wsum[31];
}

// ---------------- 3) scan finalize + inv + scaled x ---------------------------
__global__ __launch_bounds__(256) void k_scan3(const float* __restrict__ x) {
    __shared__ int sred[8];
    int t = threadIdx.x;
    int lane = t & 31, w = t >> 5;
    int k = (blockIdx.x * 256) >> 10;
    int v = (t < k && t < NBLK) ? g_bsum[t] : 0;
    #pragma unroll
    for (int o = 16; o >= 1; o >>= 1) v += __shfl_xor_sync(0xffffffffu, v, o);
    if (lane == 0) sred[w] = v;
    __syncthreads();
    if (t == 0) {
        int s = 0;
        #pragma unroll
        for (int q = 0; q < 8; q++) s += sred[q];
        sred[0] = s;
    }
    __syncthreads();
    int off = sred[0];

    int i = blockIdx.x * 256 + t;
    if (i < NN) {
        int rp = g_loc[i] + off;
        g_rowptr[i] = rp;
        g_fill[i]   = rp;
        float inv = rsqrtf((float)g_deg[i] + 1.0f);
        g_inv[i] = inv;
        float4 xv = reinterpret_cast<const float4*>(x)[i];
        xv.x *= inv; xv.y *= inv; xv.z *= inv; xv.w *= inv;
        reinterpret_cast<float4*>(g_xs)[i] = xv;
    }
}

// ---------------- 4) CSR fill (4 edges/thread, int4 loads) --------------------
__global__ void k_fill(const int* __restrict__ ei) {
    int i = blockIdx.x * blockDim.x + threadIdx.x;   // NE/4 threads
    int4 s4 = reinterpret_cast<const int4*>(ei)[i];
    int4 d4 = reinterpret_cast<const int4*>(ei)[NE / 4 + i];
    int p0 = atomicAdd(&g_fill[d4.x], 1); g_csr[p0] = s4.x;
    int p1 = atomicAdd(&g_fill[d4.y], 1); g_csr[p1] = s4.y;
    int p2 = atomicAdd(&g_fill[d4.z], 1); g_csr[p2] = s4.z;
    int p3 = atomicAdd(&g_fill[d4.w], 1); g_csr[p3] = s4.w;
}

// ---------------- 5) layer-1 gather: warp per node -----------------------------
__global__ __launch_bounds__(256) void k_gather1() {
    int node = (blockIdx.x * 256 + threadIdx.x) >> 5;
    int lane = threadIdx.x & 31;
    int start = g_rowptr[node];
    int deg   = g_deg[node];
    float4 acc = make_float4(0.f, 0.f, 0.f, 0.f);
    int j = lane;
    for (; j + 32 < deg; j += 64) {
        int s0 = g_csr[start + j];
        int s1 = g_csr[start + j + 32];
        float4 x0 = reinterpret_cast<const float4*>(g_xs)[s0];
        float4 x1 = reinterpret_cast<const float4*>(g_xs)[s1];
        acc.x += x0.x + x1.x; acc.y += x0.y + x1.y;
        acc.z += x0.z + x1.z; acc.w += x0.w + x1.w;
    }
    if (j < deg) {
        int s0 = g_csr[start + j];
        float4 x0 = reinterpret_cast<const float4*>(g_xs)[s0];
        acc.x += x0.x; acc.y += x0.y; acc.z += x0.z; acc.w += x0.w;
    }
    #pragma unroll
    for (int o = 16; o >= 1; o >>= 1) {
        acc.x += __shfl_xor_sync(0xffffffffu, acc.x, o);
        acc.y += __shfl_xor_sync(0xffffffffu, acc.y, o);
        acc.z += __shfl_xor_sync(0xffffffffu, acc.z, o);
        acc.w += __shfl_xor_sync(0xffffffffu, acc.w, o);
    }
    if (lane == 0) {
        float inv = g_inv[node];
        acc.x *= inv; acc.y *= inv; acc.z *= inv; acc.w *= inv;
        reinterpret_cast<float4*>(g_agg1)[node] = acc;
    }
}

// ---------------- 6) dense via HMMA mma.sync: hW2h = ((relu(agg@W1+b1))@W2)*inv -
// 128 threads = 4 warps. Each warp: 16 nodes/tile, 4 tiles -> 64 nodes/warp,
// 256 nodes/block. GEMM2 runs on tensor pipe (m16n8k16 f16*f16+f32).
#define L12_TILES_PER_WARP 4
#define L12_NODES_PER_BLOCK 256

__global__ __launch_bounds__(128) void k_layer12(const float* __restrict__ x,
                                                 const float* __restrict__ W1,
                                                 const float* __restrict__ b1,
                                                 const float* __restrict__ W2) {
    __shared__ float4 sW1T[128];            // W1T[k] = {W1[0][k..3][k]}
    __shared__ float  sb1[128];
    __shared__ __half sW2T[64][136];        // W2T[n][k] = W2[k][n], padded row
    __shared__ __half sA[4][16][136];       // per-warp A tile (h, fp16)

    int tid  = threadIdx.x;
    int lane = tid & 31;
    int w    = tid >> 5;

    // stage weights
    {
        float4 wv;
        wv.x = W1[0 * 128 + tid]; wv.y = W1[1 * 128 + tid];
        wv.z = W1[2 * 128 + tid]; wv.w = W1[3 * 128 + tid];
        sW1T[tid] = wv;
        sb1[tid]  = b1[tid];
    }
    for (int i = tid; i < 64 * 128; i += 128) {
        int n = i >> 7, k = i & 127;
        sW2T[n][k] = __float2half_rn(W2[k * 64 + n]);
    }
    __syncthreads();

    int g = lane >> 2;          // group 0..7
    int t = lane & 3;           // tig   0..3

    for (int it = 0; it < L12_TILES_PER_WARP; it++) {
        int base = blockIdx.x * L12_NODES_PER_BLOCK + (it * 4 + w) * 16;

        // --- build A tile: 2 lanes per node, each computes 64 h values ------
        {
            int node = base + (lane >> 1);
            int kh   = (lane & 1) * 64;
            float4 a = make_float4(0.f, 0.f, 0.f, 0.f);
            bool valid = (node < NN);
            if (valid) {
                float inv = g_inv[node];
                float i2  = inv * inv;
                a = reinterpret_cast<const float4*>(g_agg1)[node];
                float4 xv = reinterpret_cast<const float4*>(x)[node];
                a.x = fmaf(xv.x, i2, a.x);
                a.y = fmaf(xv.y, i2, a.y);
                a.z = fmaf(xv.z, i2, a.z);
                a.w = fmaf(xv.w, i2, a.w);
            }
            __half* row = &sA[w][lane >> 1][kh];
            #pragma unroll
            for (int p = 0; p < 32; p++) {
                int k2 = kh + 2 * p;
                float4 w0 = sW1T[k2];
                float4 w1 = sW1T[k2 + 1];
                float h0 = sb1[k2];
                h0 = fmaf(a.x, w0.x, h0); h0 = fmaf(a.y, w0.y, h0);
                h0 = fmaf(a.z, w0.z, h0); h0 = fmaf(a.w, w0.w, h0);
                float h1 = sb1[k2 + 1];
                h1 = fmaf(a.x, w1.x, h1); h1 = fmaf(a.y, w1.y, h1);
                h1 = fmaf(a.z, w1.z, h1); h1 = fmaf(a.w, w1.w, h1);
                __half2 hh = valid ? __floats2half2_rn(fmaxf(h0, 0.f), fmaxf(h1, 0.f))
                                   : __floats2half2_rn(0.f, 0.f);
                *reinterpret_cast<__half2*>(&row[2 * p]) = hh;
            }
        }
        __syncwarp();

        // --- 8 k-steps x 8 n-tiles of m16n8k16, all n accumulators resident --
        float d[8][4];
        #pragma unroll
        for (int nt = 0; nt < 8; nt++) {
            d[nt][0] = 0.f; d[nt][1] = 0.f; d[nt][2] = 0.f; d[nt][3] = 0.f;
        }

        #pragma unroll
        for (int kt = 0; kt < 8; kt++) {
            int k0 = kt * 16 + 2 * t;
            uint32_t a0 = *reinterpret_cast<const uint32_t*>(&sA[w][g][k0]);
            uint32_t a1 = *reinterpret_cast<const uint32_t*>(&sA[w][g + 8][k0]);
            uint32_t a2 = *reinterpret_cast<const uint32_t*>(&sA[w][g][k0 + 8]);
            uint32_t a3 = *reinterpret_cast<const uint32_t*>(&sA[w][g + 8][k0 + 8]);
            #pragma unroll
            for (int nt = 0; nt < 8; nt++) {
                int n = nt * 8 + g;
                uint32_t bb0 = *reinterpret_cast<const uint32_t*>(&sW2T[n][k0]);
                uint32_t bb1 = *reinterpret_cast<const uint32_t*>(&sW2T[n][k0 + 8]);
                asm volatile(
                    "mma.sync.aligned.m16n8k16.row.col.f32.f16.f16.f32 "
                    "{%0,%1,%2,%3}, {%4,%5,%6,%7}, {%8,%9}, {%0,%1,%2,%3};"
                    : "+f"(d[nt][0]), "+f"(d[nt][1]), "+f"(d[nt][2]), "+f"(d[nt][3])
                    : "r"(a0), "r"(a1), "r"(a2), "r"(a3), "r"(bb0), "r"(bb1));
            }
        }

        // --- epilogue: scale by inv, pack fp16, store -------------------------
        int n0 = base + g;
        int n1 = base + g + 8;
        if (n0 < NN) {
            float iv = g_inv[n0];
            #pragma unroll
            for (int nt = 0; nt < 8; nt++)
                g_hW2h[n0 * 32 + nt * 4 + t] =
                    __floats2half2_rn(d[nt][0] * iv, d[nt][1] * iv);
        }
        if (n1 < NN) {
            float iv = g_inv[n1];
            #pragma unroll
            for (int nt = 0; nt < 8; nt++)
                g_hW2h[n1 * 32 + nt * 4 + t] =
                    __floats2half2_rn(d[nt][2] * iv, d[nt][3] * iv);
        }
        __syncwarp();
    }
}

// ---------------- 7) layer-2 gather (8 lanes/node, uint4 rows) -----------------
__device__ __forceinline__ void add_h8(float* a, const uint4& v) {
    float2 f0 = __half22float2(*reinterpret_cast<const __half2*>(&v.x));
    float2 f1 = __half22float2(*reinterpret_cast<const __half2*>(&v.y));
    float2 f2 = __half22float2(*reinterpret_cast<const __half2*>(&v.z));
    float2 f3 = __half22float2(*reinterpret_cast<const __half2*>(&v.w));
    a[0] += f0.x; a[1] += f0.y; a[2] += f1.x; a[3] += f1.y;
    a[4] += f2.x; a[5] += f2.y; a[6] += f3.x; a[7] += f3.y;
}

__global__ __launch_bounds__(256) void k_gather2z(const float* __restrict__ b2) {
    unsigned t = blockIdx.x * 256u + threadIdx.x;   // NN*8 threads
    int node = t >> 3;
    int c    = t & 7;
    int start = g_rowptr[node];
    int deg   = g_deg[node];
    float inv = g_inv[node];

    const uint4* hrows = reinterpret_cast<const uint4*>(g_hW2h);  // 8 uint4 per row

    // self term: hW2 * i2 == hW2h * inv (hW2h already scaled by inv)
    float acc[8] = {0.f, 0.f, 0.f, 0.f, 0.f, 0.f, 0.f, 0.f};
    add_h8(acc, hrows[node * 8 + c]);

    int j = 0;
    for (; j + 3 < deg; j += 4) {
        int s0 = g_csr[start + j];
        int s1 = g_csr[start + j + 1];
        int s2 = g_csr[start + j + 2];
        int s3 = g_csr[start + j + 3];
        uint4 v0 = hrows[s0 * 8 + c];
        uint4 v1 = hrows[s1 * 8 + c];
        uint4 v2 = hrows[s2 * 8 + c];
        uint4 v3 = hrows[s3 * 8 + c];
        add_h8(acc, v0);
        add_h8(acc, v1);
        add_h8(acc, v2);
        add_h8(acc, v3);
    }
    for (; j < deg; j++) {
        int s0 = g_csr[start + j];
        uint4 v0 = hrows[s0 * 8 + c];
        add_h8(acc, v0);
    }

    float4 bb0 = reinterpret_cast<const float4*>(b2)[2 * c];
    float4 bb1 = reinterpret_cast<const float4*>(b2)[2 * c + 1];
    float z0 = fmaf(acc[0], inv, bb0.x);
    float z1 = fmaf(acc[1], inv, bb0.y);
    float z2 = fmaf(acc[2], inv, bb0.z);
    float z3 = fmaf(acc[3], inv, bb0.w);
    float z4 = fmaf(acc[4], inv, bb1.x);
    float z5 = fmaf(acc[5], inv, bb1.y);
    float z6 = fmaf(acc[6], inv, bb1.z);
    float z7 = fmaf(acc[7], inv, bb1.w);

    uint4 zo;
    __half2 h0 = __floats2half2_rn(z0, z1);
    __half2 h1 = __floats2half2_rn(z2, z3);
    __half2 h2 = __floats2half2_rn(z4, z5);
    __half2 h3 = __floats2half2_rn(z6, z7);
    zo.x = *reinterpret_cast<unsigned*>(&h0);
    zo.y = *reinterpret_cast<unsigned*>(&h1);
    zo.z = *reinterpret_cast<unsigned*>(&h2);
    zo.w = *reinterpret_cast<unsigned*>(&h3);
    reinterpret_cast<uint4*>(g_zh)[t] = zo;
}

// ---------------- 8) decode (8 lanes/edge, uint4) + re-zero g_deg ---------------
__global__ __launch_bounds__(256) void k_decode(const int* __restrict__ eli,
                                                float* __restrict__ out) {
    unsigned t = blockIdx.x * 256u + threadIdx.x;   // NL*8 threads
    int e = t >> 3;
    int c = t & 7;
    int a = eli[e];
    int b = eli[NL + e];
    const uint4* zr = reinterpret_cast<const uint4*>(g_zh);
    uint4 va = zr[a * 8 + c];
    uint4 vb = zr[b * 8 + c];
    float2 a0 = __half22float2(*reinterpret_cast<__half2*>(&va.x));
    float2 a1 = __half22float2(*reinterpret_cast<__half2*>(&va.y));
    float2 a2 = __half22float2(*reinterpret_cast<__half2*>(&va.z));
    float2 a3 = __half22float2(*reinterpret_cast<__half2*>(&va.w));
    float2 b0 = __half22float2(*reinterpret_cast<__half2*>(&vb.x));
    float2 b1 = __half22float2(*reinterpret_cast<__half2*>(&vb.y));
    float2 b2 = __half22float2(*reinterpret_cast<__half2*>(&vb.z));
    float2 b3 = __half22float2(*reinterpret_cast<__half2*>(&vb.w));
    float p = a0.x * b0.x + a0.y * b0.y + a1.x * b1.x + a1.y * b1.y
            + a2.x * b2.x + a2.y * b2.y + a3.x * b3.x + a3.y * b3.y;
    #pragma unroll
    for (int o = 4; o >= 1; o >>= 1) p += __shfl_xor_sync(0xffffffffu, p, o);
    if (c == 0) out[e] = p;
    if (t < NN) g_deg[t] = 0;     // restore precondition for the next replay
}

// ---------------- launch ----------------------------------------------------------
extern "C" void kernel_launch(void* const* d_in, const int* in_sizes, int n_in,
                              void* d_out, int out_size) {
    const float* x   = (const float*)d_in[0];
    const int*   ei  = (const int*)  d_in[1];
    const int*   eli = (const int*)  d_in[2];
    const float* W1  = (const float*)d_in[3];
    const float* b1  = (const float*)d_in[4];
    const float* W2  = (const float*)d_in[5];
    const float* b2  = (const float*)d_in[6];
    float* out = (float*)d_out;

    k_deg     <<<NE / 4 / 256, 256>>>(ei);
    k_scan1   <<<NBLK, SCAN_B>>>();
    k_scan3   <<<(NN + 255) / 256, 256>>>(x);
    k_fill    <<<NE / 4 / 256, 256>>>(ei);
    k_gather1 <<<NN * 32 / 256, 256>>>();
    k_layer12 <<<(NN + L12_NODES_PER_BLOCK - 1) / L12_NODES_PER_BLOCK, 128>>>(x, W1, b1, W2);
    k_gather2z<<<NN * 8 / 256, 256>>>(b2);
    k_decode  <<<NL * 8 / 256, 256>>>(eli, out);
}

// round 10
// speedup vs baseline: 2.2772x; 1.1132x over previous
#include <cuda_runtime.h>
#include <cuda_fp16.h>
#include <cstdint>

#define NN 100000
#define NE 3200000
#define NL 200000
#define CAP 128                 // padded CSR slots per node (mean deg 32, P(>128)~1e-37)

// ---------------- scratch (device globals) ----------------------------------
__device__ int                  g_deg[NN];      // zero-init at load; re-zeroed by k_decode
__device__ float                g_inv[NN];
__device__ int                  g_csr[NN * CAP];    // padded, dst-grouped src ids
__device__ __align__(16) float  g_xs[NN * 4];       // x * inv[s]
__device__ __align__(16) float  g_agg1[NN * 4];
__device__ __align__(16) __half2 g_hW2h[NN * 32];   // fp16, scaled by inv[s]
__device__ __align__(16) __half g_zh[NN * 64];      // fp16 z (decode table)

// ---------------- 1) fused degree-count + CSR fill (4 edges/thread, exact grid) -
__global__ void k_fill(const int* __restrict__ ei) {
    int i = blockIdx.x * blockDim.x + threadIdx.x;   // NE/4 threads (3125 blocks exact)
    int4 s4 = reinterpret_cast<const int4*>(ei)[i];
    int4 d4 = reinterpret_cast<const int4*>(ei)[NE / 4 + i];
    int p;
    p = atomicAdd(&g_deg[d4.x], 1); g_csr[(d4.x << 7) + p] = s4.x;
    p = atomicAdd(&g_deg[d4.y], 1); g_csr[(d4.y << 7) + p] = s4.y;
    p = atomicAdd(&g_deg[d4.z], 1); g_csr[(d4.z << 7) + p] = s4.z;
    p = atomicAdd(&g_deg[d4.w], 1); g_csr[(d4.w << 7) + p] = s4.w;
}

// ---------------- 2) inv + scaled x -------------------------------------------
__global__ __launch_bounds__(256) void k_prep(const float* __restrict__ x) {
    int i = blockIdx.x * 256 + threadIdx.x;
    if (i < NN) {
        float inv = rsqrtf((float)g_deg[i] + 1.0f);
        g_inv[i] = inv;
        float4 xv = reinterpret_cast<const float4*>(x)[i];
        xv.x *= inv; xv.y *= inv; xv.z *= inv; xv.w *= inv;
        reinterpret_cast<float4*>(g_xs)[i] = xv;
    }
}

// ---------------- 3) layer-1 gather: warp per node -----------------------------
__global__ __launch_bounds__(256) void k_gather1() {
    int node = (blockIdx.x * 256 + threadIdx.x) >> 5;
    int lane = threadIdx.x & 31;
    int start = node << 7;
    int deg   = g_deg[node];
    float4 acc = make_float4(0.f, 0.f, 0.f, 0.f);
    int j = lane;
    for (; j + 32 < deg; j += 64) {
        int s0 = g_csr[start + j];
        int s1 = g_csr[start + j + 32];
        float4 x0 = reinterpret_cast<const float4*>(g_xs)[s0];
        float4 x1 = reinterpret_cast<const float4*>(g_xs)[s1];
        acc.x += x0.x + x1.x; acc.y += x0.y + x1.y;
        acc.z += x0.z + x1.z; acc.w += x0.w + x1.w;
    }
    if (j < deg) {
        int s0 = g_csr[start + j];
        float4 x0 = reinterpret_cast<const float4*>(g_xs)[s0];
        acc.x += x0.x; acc.y += x0.y; acc.z += x0.z; acc.w += x0.w;
    }
    #pragma unroll
    for (int o = 16; o >= 1; o >>= 1) {
        acc.x += __shfl_xor_sync(0xffffffffu, acc.x, o);
        acc.y += __shfl_xor_sync(0xffffffffu, acc.y, o);
        acc.z += __shfl_xor_sync(0xffffffffu, acc.z, o);
        acc.w += __shfl_xor_sync(0xffffffffu, acc.w, o);
    }
    if (lane == 0) {
        float inv = g_inv[node];
        acc.x *= inv; acc.y *= inv; acc.z *= inv; acc.w *= inv;
        reinterpret_cast<float4*>(g_agg1)[node] = acc;
    }
}

// ---------------- 4) dense via HMMA mma.sync: hW2h = ((relu(agg@W1+b1))@W2)*inv -
#define L12_TILES_PER_WARP 4
#define L12_NODES_PER_BLOCK 256

__global__ __launch_bounds__(128) void k_layer12(const float* __restrict__ x,
                                                 const float* __restrict__ W1,
                                                 const float* __restrict__ b1,
                                                 const float* __restrict__ W2) {
    __shared__ float4 sW1T[128];            // W1T[k] = {W1[0..3][k]}
    __shared__ float  sb1[128];
    __shared__ __half sW2T[64][136];        // W2T[n][k] = W2[k][n], padded row
    __shared__ __half sA[4][16][136];       // per-warp A tile (h, fp16)

    int tid  = threadIdx.x;
    int lane = tid & 31;
    int w    = tid >> 5;

    {
        float4 wv;
        wv.x = W1[0 * 128 + tid]; wv.y = W1[1 * 128 + tid];
        wv.z = W1[2 * 128 + tid]; wv.w = W1[3 * 128 + tid];
        sW1T[tid] = wv;
        sb1[tid]  = b1[tid];
    }
    for (int i = tid; i < 64 * 128; i += 128) {
        int n = i >> 7, k = i & 127;
        sW2T[n][k] = __float2half_rn(W2[k * 64 + n]);
    }
    __syncthreads();

    int g = lane >> 2;          // 0..7
    int t = lane & 3;           // 0..3

    for (int it = 0; it < L12_TILES_PER_WARP; it++) {
        int base = blockIdx.x * L12_NODES_PER_BLOCK + (it * 4 + w) * 16;

        // --- build A tile: 2 lanes per node, each computes 64 h values ------
        {
            int node = base + (lane >> 1);
            int kh   = (lane & 1) * 64;
            float4 a = make_float4(0.f, 0.f, 0.f, 0.f);
            bool valid = (node < NN);
            if (valid) {
                float inv = g_inv[node];
                float i2  = inv * inv;
                a = reinterpret_cast<const float4*>(g_agg1)[node];
                float4 xv = reinterpret_cast<const float4*>(x)[node];
                a.x = fmaf(xv.x, i2, a.x);
                a.y = fmaf(xv.y, i2, a.y);
                a.z = fmaf(xv.z, i2, a.z);
                a.w = fmaf(xv.w, i2, a.w);
            }
            __half* row = &sA[w][lane >> 1][kh];
            #pragma unroll
            for (int p = 0; p < 32; p++) {
                int k2 = kh + 2 * p;
                float4 w0 = sW1T[k2];
                float4 w1 = sW1T[k2 + 1];
                float h0 = sb1[k2];
                h0 = fmaf(a.x, w0.x, h0); h0 = fmaf(a.y, w0.y, h0);
                h0 = fmaf(a.z, w0.z, h0); h0 = fmaf(a.w, w0.w, h0);
                float h1 = sb1[k2 + 1];
                h1 = fmaf(a.x, w1.x, h1); h1 = fmaf(a.y, w1.y, h1);
                h1 = fmaf(a.z, w1.z, h1); h1 = fmaf(a.w, w1.w, h1);
                __half2 hh = valid ? __floats2half2_rn(fmaxf(h0, 0.f), fmaxf(h1, 0.f))
                                   : __floats2half2_rn(0.f, 0.f);
                *reinterpret_cast<__half2*>(&row[2 * p]) = hh;
            }
        }
        __syncwarp();

        // --- 8 k-steps x 8 n-tiles of m16n8k16 --------------------------------
        float d[8][4];
        #pragma unroll
        for (int nt = 0; nt < 8; nt++) {
            d[nt][0] = 0.f; d[nt][1] = 0.f; d[nt][2] = 0.f; d[nt][3] = 0.f;
        }

        #pragma unroll
        for (int kt = 0; kt < 8; kt++) {
            int k0 = kt * 16 + 2 * t;
            uint32_t a0 = *reinterpret_cast<const uint32_t*>(&sA[w][g][k0]);
            uint32_t a1 = *reinterpret_cast<const uint32_t*>(&sA[w][g + 8][k0]);
            uint32_t a2 = *reinterpret_cast<const uint32_t*>(&sA[w][g][k0 + 8]);
            uint32_t a3 = *reinterpret_cast<const uint32_t*>(&sA[w][g + 8][k0 + 8]);
            #pragma unroll
            for (int nt = 0; nt < 8; nt++) {
                int n = nt * 8 + g;
                uint32_t bb0 = *reinterpret_cast<const uint32_t*>(&sW2T[n][k0]);
                uint32_t bb1 = *reinterpret_cast<const uint32_t*>(&sW2T[n][k0 + 8]);
                asm volatile(
                    "mma.sync.aligned.m16n8k16.row.col.f32.f16.f16.f32 "
                    "{%0,%1,%2,%3}, {%4,%5,%6,%7}, {%8,%9}, {%0,%1,%2,%3};"
                    : "+f"(d[nt][0]), "+f"(d[nt][1]), "+f"(d[nt][2]), "+f"(d[nt][3])
                    : "r"(a0), "r"(a1), "r"(a2), "r"(a3), "r"(bb0), "r"(bb1));
            }
        }

        // --- epilogue ----------------------------------------------------------
        int n0 = base + g;
        int n1 = base + g + 8;
        if (n0 < NN) {
            float iv = g_inv[n0];
            #pragma unroll
            for (int nt = 0; nt < 8; nt++)
                g_hW2h[n0 * 32 + nt * 4 + t] =
                    __floats2half2_rn(d[nt][0] * iv, d[nt][1] * iv);
        }
        if (n1 < NN) {
            float iv = g_inv[n1];
            #pragma unroll
            for (int nt = 0; nt < 8; nt++)
                g_hW2h[n1 * 32 + nt * 4 + t] =
                    __floats2half2_rn(d[nt][2] * iv, d[nt][3] * iv);
        }
        __syncwarp();
    }
}

// ---------------- 5) layer-2 gather (8 lanes/node, uint4 rows) -----------------
__device__ __forceinline__ void add_h8(float* a, const uint4& v) {
    float2 f0 = __half22float2(*reinterpret_cast<const __half2*>(&v.x));
    float2 f1 = __half22float2(*reinterpret_cast<const __half2*>(&v.y));
    float2 f2 = __half22float2(*reinterpret_cast<const __half2*>(&v.z));
    float2 f3 = __half22float2(*reinterpret_cast<const __half2*>(&v.w));
    a[0] += f0.x; a[1] += f0.y; a[2] += f1.x; a[3] += f1.y;
    a[4] += f2.x; a[5] += f2.y; a[6] += f3.x; a[7] += f3.y;
}

__global__ __launch_bounds__(256) void k_gather2z(const float* __restrict__ b2) {
    unsigned t = blockIdx.x * 256u + threadIdx.x;   // NN*8 threads
    int node = t >> 3;
    int c    = t & 7;
    int start = node << 7;
    int deg   = g_deg[node];
    float inv = g_inv[node];

    const uint4* hrows = reinterpret_cast<const uint4*>(g_hW2h);  // 8 uint4 per row

    // self term: hW2 * i2 == hW2h * inv (hW2h already scaled by inv)
    float acc[8] = {0.f, 0.f, 0.f, 0.f, 0.f, 0.f, 0.f, 0.f};
    add_h8(acc, hrows[node * 8 + c]);

    int j = 0;
    for (; j + 3 < deg; j += 4) {
        int s0 = g_csr[start + j];
        int s1 = g_csr[start + j + 1];
        int s2 = g_csr[start + j + 2];
        int s3 = g_csr[start + j + 3];
        uint4 v0 = hrows[s0 * 8 + c];
        uint4 v1 = hrows[s1 * 8 + c];
        uint4 v2 = hrows[s2 * 8 + c];
        uint4 v3 = hrows[s3 * 8 + c];
        add_h8(acc, v0);
        add_h8(acc, v1);
        add_h8(acc, v2);
        add_h8(acc, v3);
    }
    for (; j < deg; j++) {
        int s0 = g_csr[start + j];
        uint4 v0 = hrows[s0 * 8 + c];
        add_h8(acc, v0);
    }

    float4 bb0 = reinterpret_cast<const float4*>(b2)[2 * c];
    float4 bb1 = reinterpret_cast<const float4*>(b2)[2 * c + 1];
    float z0 = fmaf(acc[0], inv, bb0.x);
    float z1 = fmaf(acc[1], inv, bb0.y);
    float z2 = fmaf(acc[2], inv, bb0.z);
    float z3 = fmaf(acc[3], inv, bb0.w);
    float z4 = fmaf(acc[4], inv, bb1.x);
    float z5 = fmaf(acc[5], inv, bb1.y);
    float z6 = fmaf(acc[6], inv, bb1.z);
    float z7 = fmaf(acc[7], inv, bb1.w);

    uint4 zo;
    __half2 h0 = __floats2half2_rn(z0, z1);
    __half2 h1 = __floats2half2_rn(z2, z3);
    __half2 h2 = __floats2half2_rn(z4, z5);
    __half2 h3 = __floats2half2_rn(z6, z7);
    zo.x = *reinterpret_cast<unsigned*>(&h0);
    zo.y = *reinterpret_cast<unsigned*>(&h1);
    zo.z = *reinterpret_cast<unsigned*>(&h2);
    zo.w = *reinterpret_cast<unsigned*>(&h3);
    reinterpret_cast<uint4*>(g_zh)[t] = zo;
}

// ---------------- 6) decode (8 lanes/edge, uint4) + re-zero g_deg ---------------
__global__ __launch_bounds__(256) void k_decode(const int* __restrict__ eli,
                                                float* __restrict__ out) {
    unsigned t = blockIdx.x * 256u + threadIdx.x;   // NL*8 threads
    int e = t >> 3;
    int c = t & 7;
    int a = eli[e];
    int b = eli[NL + e];
    const uint4* zr = reinterpret_cast<const uint4*>(g_zh);
    uint4 va = zr[a * 8 + c];
    uint4 vb = zr[b * 8 + c];
    float2 a0 = __half22float2(*reinterpret_cast<__half2*>(&va.x));
    float2 a1 = __half22float2(*reinterpret_cast<__half2*>(&va.y));
    float2 a2 = __half22float2(*reinterpret_cast<__half2*>(&va.z));
    float2 a3 = __half22float2(*reinterpret_cast<__half2*>(&va.w));
    float2 b0 = __half22float2(*reinterpret_cast<__half2*>(&vb.x));
    float2 b1 = __half22float2(*reinterpret_cast<__half2*>(&vb.y));
    float2 b2 = __half22float2(*reinterpret_cast<__half2*>(&vb.z));
    float2 b3 = __half22float2(*reinterpret_cast<__half2*>(&vb.w));
    float p = a0.x * b0.x + a0.y * b0.y + a1.x * b1.x + a1.y * b1.y
            + a2.x * b2.x + a2.y * b2.y + a3.x * b3.x + a3.y * b3.y;
    #pragma unroll
    for (int o = 4; o >= 1; o >>= 1) p += __shfl_xor_sync(0xffffffffu, p, o);
    if (c == 0) out[e] = p;
    if (t < NN) g_deg[t] = 0;     // restore precondition for the next replay
}

// ---------------- launch ----------------------------------------------------------
extern "C" void kernel_launch(void* const* d_in, const int* in_sizes, int n_in,
                              void* d_out, int out_size) {
    const float* x   = (const float*)d_in[0];
    const int*   ei  = (const int*)  d_in[1];
    const int*   eli = (const int*)  d_in[2];
    const float* W1  = (const float*)d_in[3];
    const float* b1  = (const float*)d_in[4];
    const float* W2  = (const float*)d_in[5];
    const float* b2  = (const float*)d_in[6];
    float* out = (float*)d_out;

    k_fill    <<<NE / 4 / 256, 256>>>(ei);       // 3125 blocks, exact
    k_prep    <<<(NN + 255) / 256, 256>>>(x);
    k_gather1 <<<NN * 32 / 256, 256>>>();
    k_layer12 <<<(NN + L12_NODES_PER_BLOCK - 1) / L12_NODES_PER_BLOCK, 128>>>(x, W1, b1, W2);
    k_gather2z<<<NN * 8 / 256, 256>>>(b2);
    k_decode  <<<NL * 8 / 256, 256>>>(eli, out);
}

// round 11
// speedup vs baseline: 2.4097x; 1.0582x over previous
#include <cuda_runtime.h>
#include <cuda_fp16.h>
#include <cstdint>

#define NN 100000
#define NE 3200000
#define NL 200000
#define CAP 128                 // padded CSR slots per node (mean deg 32, P(>128)~1e-37)

// ---------------- scratch (device globals) ----------------------------------
__device__ int                  g_deg[NN];      // zero-init at load; re-zeroed by k_decode
__device__ float                g_inv[NN];
__device__ int                  g_csr[NN * CAP];    // padded, dst-grouped src ids
__device__ __align__(16) float  g_xs[NN * 4];       // x * inv[s]
__device__ __align__(16) float  g_agg1[NN * 4];
__device__ __align__(16) __half2 g_hW2h[NN * 32];   // fp16, scaled by inv[s]
__device__ __align__(16) __half g_zh[NN * 64];      // fp16 z (decode table)

// ---------------- 1) fused degree-count + CSR fill (4 edges/thread, exact grid) -
__global__ void k_fill(const int* __restrict__ ei) {
    int i = blockIdx.x * blockDim.x + threadIdx.x;   // NE/4 threads (3125 blocks exact)
    int4 s4 = reinterpret_cast<const int4*>(ei)[i];
    int4 d4 = reinterpret_cast<const int4*>(ei)[NE / 4 + i];
    int p;
    p = atomicAdd(&g_deg[d4.x], 1); g_csr[(d4.x << 7) + p] = s4.x;
    p = atomicAdd(&g_deg[d4.y], 1); g_csr[(d4.y << 7) + p] = s4.y;
    p = atomicAdd(&g_deg[d4.z], 1); g_csr[(d4.z << 7) + p] = s4.z;
    p = atomicAdd(&g_deg[d4.w], 1); g_csr[(d4.w << 7) + p] = s4.w;
}

// ---------------- 2) inv + scaled x -------------------------------------------
__global__ __launch_bounds__(256) void k_prep(const float* __restrict__ x) {
    int i = blockIdx.x * 256 + threadIdx.x;
    if (i < NN) {
        float inv = rsqrtf((float)g_deg[i] + 1.0f);
        g_inv[i] = inv;
        float4 xv = reinterpret_cast<const float4*>(x)[i];
        xv.x *= inv; xv.y *= inv; xv.z *= inv; xv.w *= inv;
        reinterpret_cast<float4*>(g_xs)[i] = xv;
    }
}

// ---------------- 3) layer-1 gather: warp per node -----------------------------
__global__ __launch_bounds__(256) void k_gather1() {
    int node = (blockIdx.x * 256 + threadIdx.x) >> 5;
    int lane = threadIdx.x & 31;
    int start = node << 7;
    int deg   = g_deg[node];
    float4 acc = make_float4(0.f, 0.f, 0.f, 0.f);
    int j = lane;
    for (; j + 32 < deg; j += 64) {
        int s0 = g_csr[start + j];
        int s1 = g_csr[start + j + 32];
        float4 x0 = reinterpret_cast<const float4*>(g_xs)[s0];
        float4 x1 = reinterpret_cast<const float4*>(g_xs)[s1];
        acc.x += x0.x + x1.x; acc.y += x0.y + x1.y;
        acc.z += x0.z + x1.z; acc.w += x0.w + x1.w;
    }
    if (j < deg) {
        int s0 = g_csr[start + j];
        float4 x0 = reinterpret_cast<const float4*>(g_xs)[s0];
        acc.x += x0.x; acc.y += x0.y; acc.z += x0.z; acc.w += x0.w;
    }
    #pragma unroll
    for (int o = 16; o >= 1; o >>= 1) {
        acc.x += __shfl_xor_sync(0xffffffffu, acc.x, o);
        acc.y += __shfl_xor_sync(0xffffffffu, acc.y, o);
        acc.z += __shfl_xor_sync(0xffffffffu, acc.z, o);
        acc.w += __shfl_xor_sync(0xffffffffu, acc.w, o);
    }
    if (lane == 0) {
        float inv = g_inv[node];
        acc.x *= inv; acc.y *= inv; acc.z *= inv; acc.w *= inv;
        reinterpret_cast<float4*>(g_agg1)[node] = acc;
    }
}

// ---------------- 4) dense via HMMA, A fragments computed in registers ----------
// 256 threads = 8 warps; each warp does 2 tiles of 16 nodes -> 256 nodes/block.
// Lane (g,t) computes h for its OWN fragment rows (g, g+8) at its OWN fragment
// columns, so no smem A tile, no STS/LDS round trip, no syncwarp.
#define L12_NODES_PER_BLOCK 256

__global__ __launch_bounds__(256) void k_layer12(const float* __restrict__ x,
                                                 const float* __restrict__ W1,
                                                 const float* __restrict__ b1,
                                                 const float* __restrict__ W2) {
    __shared__ float4 sW1T[128];            // W1T[k] = {W1[0..3][k]}
    __shared__ float  sb1[128];
    __shared__ __half sW2T[64][136];        // W2T[n][k] = W2[k][n], padded row

    int tid  = threadIdx.x;
    int lane = tid & 31;
    int w    = tid >> 5;

    if (tid < 128) {
        float4 wv;
        wv.x = W1[0 * 128 + tid]; wv.y = W1[1 * 128 + tid];
        wv.z = W1[2 * 128 + tid]; wv.w = W1[3 * 128 + tid];
        sW1T[tid] = wv;
        sb1[tid]  = b1[tid];
    }
    for (int i = tid; i < 64 * 128; i += 256) {
        int n = i >> 7, k = i & 127;
        sW2T[n][k] = __float2half_rn(W2[k * 64 + n]);
    }
    __syncthreads();

    int g = lane >> 2;          // 0..7 (fragment row group)
    int t = lane & 3;           // 0..3 (fragment column group)

    #pragma unroll
    for (int it = 0; it < 2; it++) {
        int base = blockIdx.x * L12_NODES_PER_BLOCK + (it * 8 + w) * 16;
        int n0 = base + g;
        int n1 = base + g + 8;
        bool v0 = (n0 < NN), v1 = (n1 < NN);

        // load aggregated inputs for this lane's two fragment rows
        float4 A0 = make_float4(0.f, 0.f, 0.f, 0.f);
        float4 A1 = make_float4(0.f, 0.f, 0.f, 0.f);
        float iv0 = 0.f, iv1 = 0.f;
        if (v0) {
            iv0 = g_inv[n0];
            float i2 = iv0 * iv0;
            A0 = reinterpret_cast<const float4*>(g_agg1)[n0];
            float4 xv = reinterpret_cast<const float4*>(x)[n0];
            A0.x = fmaf(xv.x, i2, A0.x); A0.y = fmaf(xv.y, i2, A0.y);
            A0.z = fmaf(xv.z, i2, A0.z); A0.w = fmaf(xv.w, i2, A0.w);
        }
        if (v1) {
            iv1 = g_inv[n1];
            float i2 = iv1 * iv1;
            A1 = reinterpret_cast<const float4*>(g_agg1)[n1];
            float4 xv = reinterpret_cast<const float4*>(x)[n1];
            A1.x = fmaf(xv.x, i2, A1.x); A1.y = fmaf(xv.y, i2, A1.y);
            A1.z = fmaf(xv.z, i2, A1.z); A1.w = fmaf(xv.w, i2, A1.w);
        }

        float d[8][4];
        #pragma unroll
        for (int nt = 0; nt < 8; nt++) {
            d[nt][0] = 0.f; d[nt][1] = 0.f; d[nt][2] = 0.f; d[nt][3] = 0.f;
        }

        #pragma unroll
        for (int kt = 0; kt < 8; kt++) {
            int c0 = kt * 16 + 2 * t;       // fragment cols c0, c0+1
            int c2 = c0 + 8;                // fragment cols c2, c2+1

            float4 wa = sW1T[c0], wb = sW1T[c0 + 1];
            float4 wc = sW1T[c2], wd = sW1T[c2 + 1];
            float ba = sb1[c0], bb = sb1[c0 + 1], bc = sb1[c2], bd = sb1[c2 + 1];

            // h(node, col) = relu(b1[col] + dot(A, W1T[col]))
            float h00 = ba, h01 = bb, h02 = bc, h03 = bd;    // node n0
            h00 = fmaf(A0.x, wa.x, h00); h00 = fmaf(A0.y, wa.y, h00);
            h00 = fmaf(A0.z, wa.z, h00); h00 = fmaf(A0.w, wa.w, h00);
            h01 = fmaf(A0.x, wb.x, h01); h01 = fmaf(A0.y, wb.y, h01);
            h01 = fmaf(A0.z, wb.z, h01); h01 = fmaf(A0.w, wb.w, h01);
            h02 = fmaf(A0.x, wc.x, h02); h02 = fmaf(A0.y, wc.y, h02);
            h02 = fmaf(A0.z, wc.z, h02); h02 = fmaf(A0.w, wc.w, h02);
            h03 = fmaf(A0.x, wd.x, h03); h03 = fmaf(A0.y, wd.y, h03);
            h03 = fmaf(A0.z, wd.z, h03); h03 = fmaf(A0.w, wd.w, h03);

            float h10 = ba, h11 = bb, h12 = bc, h13 = bd;    // node n1
            h10 = fmaf(A1.x, wa.x, h10); h10 = fmaf(A1.y, wa.y, h10);
            h10 = fmaf(A1.z, wa.z, h10); h10 = fmaf(A1.w, wa.w, h10);
            h11 = fmaf(A1.x, wb.x, h11); h11 = fmaf(A1.y, wb.y, h11);
            h11 = fmaf(A1.z, wb.z, h11); h11 = fmaf(A1.w, wb.w, h11);
            h12 = fmaf(A1.x, wc.x, h12); h12 = fmaf(A1.y, wc.y, h12);
            h12 = fmaf(A1.z, wc.z, h12); h12 = fmaf(A1.w, wc.w, h12);
            h13 = fmaf(A1.x, wd.x, h13); h13 = fmaf(A1.y, wd.y, h13);
            h13 = fmaf(A1.z, wd.z, h13); h13 = fmaf(A1.w, wd.w, h13);

            __half2 f0 = __floats2half2_rn(fmaxf(h00, 0.f), fmaxf(h01, 0.f));
            __half2 f1 = __floats2half2_rn(fmaxf(h10, 0.f), fmaxf(h11, 0.f));
            __half2 f2 = __floats2half2_rn(fmaxf(h02, 0.f), fmaxf(h03, 0.f));
            __half2 f3 = __floats2half2_rn(fmaxf(h12, 0.f), fmaxf(h13, 0.f));
            uint32_t a0 = *reinterpret_cast<uint32_t*>(&f0);
            uint32_t a1 = *reinterpret_cast<uint32_t*>(&f1);
            uint32_t a2 = *reinterpret_cast<uint32_t*>(&f2);
            uint32_t a3 = *reinterpret_cast<uint32_t*>(&f3);

            int k0 = kt * 16 + 2 * t;
            #pragma unroll
            for (int nt = 0; nt < 8; nt++) {
                int n = nt * 8 + g;
                uint32_t bb0 = *reinterpret_cast<const uint32_t*>(&sW2T[n][k0]);
                uint32_t bb1 = *reinterpret_cast<const uint32_t*>(&sW2T[n][k0 + 8]);
                asm volatile(
                    "mma.sync.aligned.m16n8k16.row.col.f32.f16.f16.f32 "
                    "{%0,%1,%2,%3}, {%4,%5,%6,%7}, {%8,%9}, {%0,%1,%2,%3};"
                    : "+f"(d[nt][0]), "+f"(d[nt][1]), "+f"(d[nt][2]), "+f"(d[nt][3])
                    : "r"(a0), "r"(a1), "r"(a2), "r"(a3), "r"(bb0), "r"(bb1));
            }
        }

        // --- epilogue: rows match this lane's fragment rows -----------------
        if (v0) {
            #pragma unroll
            for (int nt = 0; nt < 8; nt++)
                g_hW2h[n0 * 32 + nt * 4 + t] =
                    __floats2half2_rn(d[nt][0] * iv0, d[nt][1] * iv0);
        }
        if (v1) {
            #pragma unroll
            for (int nt = 0; nt < 8; nt++)
                g_hW2h[n1 * 32 + nt * 4 + t] =
                    __floats2half2_rn(d[nt][2] * iv1, d[nt][3] * iv1);
        }
    }
}

// ---------------- 5) layer-2 gather (8 lanes/node, uint4 rows) -----------------
__device__ __forceinline__ void add_h8(float* a, const uint4& v) {
    float2 f0 = __half22float2(*reinterpret_cast<const __half2*>(&v.x));
    float2 f1 = __half22float2(*reinterpret_cast<const __half2*>(&v.y));
    float2 f2 = __half22float2(*reinterpret_cast<const __half2*>(&v.z));
    float2 f3 = __half22float2(*reinterpret_cast<const __half2*>(&v.w));
    a[0] += f0.x; a[1] += f0.y; a[2] += f1.x; a[3] += f1.y;
    a[4] += f2.x; a[5] += f2.y; a[6] += f3.x; a[7] += f3.y;
}

__global__ __launch_bounds__(256) void k_gather2z(const float* __restrict__ b2) {
    unsigned t = blockIdx.x * 256u + threadIdx.x;   // NN*8 threads
    int node = t >> 3;
    int c    = t & 7;
    int start = node << 7;
    int deg   = g_deg[node];
    float inv = g_inv[node];

    const uint4* hrows = reinterpret_cast<const uint4*>(g_hW2h);  // 8 uint4 per row

    // self term: hW2 * i2 == hW2h * inv (hW2h already scaled by inv)
    float acc[8] = {0.f, 0.f, 0.f, 0.f, 0.f, 0.f, 0.f, 0.f};
    add_h8(acc, hrows[node * 8 + c]);

    int j = 0;
    for (; j + 3 < deg; j += 4) {
        int s0 = g_csr[start + j];
        int s1 = g_csr[start + j + 1];
        int s2 = g_csr[start + j + 2];
        int s3 = g_csr[start + j + 3];
        uint4 v0 = hrows[s0 * 8 + c];
        uint4 v1 = hrows[s1 * 8 + c];
        uint4 v2 = hrows[s2 * 8 + c];
        uint4 v3 = hrows[s3 * 8 + c];
        add_h8(acc, v0);
        add_h8(acc, v1);
        add_h8(acc, v2);
        add_h8(acc, v3);
    }
    for (; j < deg; j++) {
        int s0 = g_csr[start + j];
        uint4 v0 = hrows[s0 * 8 + c];
        add_h8(acc, v0);
    }

    float4 bb0 = reinterpret_cast<const float4*>(b2)[2 * c];
    float4 bb1 = reinterpret_cast<const float4*>(b2)[2 * c + 1];
    float z0 = fmaf(acc[0], inv, bb0.x);
    float z1 = fmaf(acc[1], inv, bb0.y);
    float z2 = fmaf(acc[2], inv, bb0.z);
    float z3 = fmaf(acc[3], inv, bb0.w);
    float z4 = fmaf(acc[4], inv, bb1.x);
    float z5 = fmaf(acc[5], inv, bb1.y);
    float z6 = fmaf(acc[6], inv, bb1.z);
    float z7 = fmaf(acc[7], inv, bb1.w);

    uint4 zo;
    __half2 h0 = __floats2half2_rn(z0, z1);
    __half2 h1 = __floats2half2_rn(z2, z3);
    __half2 h2 = __floats2half2_rn(z4, z5);
    __half2 h3 = __floats2half2_rn(z6, z7);
    zo.x = *reinterpret_cast<unsigned*>(&h0);
    zo.y = *reinterpret_cast<unsigned*>(&h1);
    zo.z = *reinterpret_cast<unsigned*>(&h2);
    zo.w = *reinterpret_cast<unsigned*>(&h3);
    reinterpret_cast<uint4*>(g_zh)[t] = zo;
}

// ---------------- 6) decode (8 lanes/edge, uint4) + re-zero g_deg ---------------
__global__ __launch_bounds__(256) void k_decode(const int* __restrict__ eli,
                                                float* __restrict__ out) {
    unsigned t = blockIdx.x * 256u + threadIdx.x;   // NL*8 threads
    int e = t >> 3;
    int c = t & 7;
    int a = eli[e];
    int b = eli[NL + e];
    const uint4* zr = reinterpret_cast<const uint4*>(g_zh);
    uint4 va = zr[a * 8 + c];
    uint4 vb = zr[b * 8 + c];
    float2 a0 = __half22float2(*reinterpret_cast<__half2*>(&va.x));
    float2 a1 = __half22float2(*reinterpret_cast<__half2*>(&va.y));
    float2 a2 = __half22float2(*reinterpret_cast<__half2*>(&va.z));
    float2 a3 = __half22float2(*reinterpret_cast<__half2*>(&va.w));
    float2 b0 = __half22float2(*reinterpret_cast<__half2*>(&vb.x));
    float2 b1 = __half22float2(*reinterpret_cast<__half2*>(&vb.y));
    float2 b2 = __half22float2(*reinterpret_cast<__half2*>(&vb.z));
    float2 b3 = __half22float2(*reinterpret_cast<__half2*>(&vb.w));
    float p = a0.x * b0.x + a0.y * b0.y + a1.x * b1.x + a1.y * b1.y
            + a2.x * b2.x + a2.y * b2.y + a3.x * b3.x + a3.y * b3.y;
    #pragma unroll
    for (int o = 4; o >= 1; o >>= 1) p += __shfl_xor_sync(0xffffffffu, p, o);
    if (c == 0) out[e] = p;
    if (t < NN) g_deg[t] = 0;     // restore precondition for the next replay
}

// ---------------- launch ----------------------------------------------------------
extern "C" void kernel_launch(void* const* d_in, const int* in_sizes, int n_in,
                              void* d_out, int out_size) {
    const float* x   = (const float*)d_in[0];
    const int*   ei  = (const int*)  d_in[1];
    const int*   eli = (const int*)  d_in[2];
    const float* W1  = (const float*)d_in[3];
    const float* b1  = (const float*)d_in[4];
    const float* W2  = (const float*)d_in[5];
    const float* b2  = (const float*)d_in[6];
    float* out = (float*)d_out;

    k_fill    <<<NE / 4 / 256, 256>>>(ei);       // 3125 blocks, exact
    k_prep    <<<(NN + 255) / 256, 256>>>(x);
    k_gather1 <<<NN * 32 / 256, 256>>>();
    k_layer12 <<<(NN + L12_NODES_PER_BLOCK - 1) / L12_NODES_PER_BLOCK, 256>>>(x, W1, b1, W2);
    k_gather2z<<<NN * 8 / 256, 256>>>(b2);
    k_decode  <<<NL * 8 / 256, 256>>>(eli, out);
}